// round 10
// baseline (speedup 1.0000x reference)
#include <cuda_runtime.h>
#include <cuda_fp16.h>
#include <math.h>
#include <stdint.h>

// Problem constants (fixed by the dataset)
#define NN    50000
#define EE    800000
#define ETOT  850000        // EE + NN self loops
#define FIN   256
#define HH    4
#define CC1   128
#define CC2   64
#define CH1   512           // HH*CC1
#define CH2   256           // HH*CC2
#define NCLS  50
#define SLOPE 0.2f
#define NBLK  ((NN + 255) / 256)

// ---------------- scratch (device globals; no allocations allowed) ----------
__device__ __half g_xh [NN * FIN];    // x   in fp16 (GEMM1 A)
__device__ __half g_W1h[FIN * CH1];   // W1  fp16
__device__ __half g_W2h[CH1 * CH2];   // W2  fp16
__device__ __half g_Wfh[CH2 * 128];   // Wf  fp16, zero-padded to 128 cols
__device__ __half g_h1h[NN * CH1];    // x @ W1  (messages, fp16)
__device__ __half g_h2h[NN * CH2];    // g1 @ W2 (messages, fp16)
__device__ __half g_g1h[NN * CH1];    // elu(agg1 + b1), fp16 (GEMM2 A)
__device__ __half g_g2h[NN * CH2];    // elu(agg2 + b2), fp16 (GEMM3 A)
__device__ float g_asrc[NN * HH];
__device__ float g_adst[NN * HH];
__device__ int   g_deg[NN];
__device__ int   g_rowptr[NN + 1];
__device__ int   g_cursor[NN];
__device__ int   g_csr[ETOT];
__device__ int   g_blocksum[256];
__device__ int   g_blockoff[256];

// ---------------- CSR construction ------------------------------------------
__global__ void zero_deg_kernel() {
    int i = blockIdx.x * blockDim.x + threadIdx.x;
    if (i < NN) g_deg[i] = 0;
}

__global__ void count_deg_kernel(const int* __restrict__ ei) {
    int e = blockIdx.x * blockDim.x + threadIdx.x;
    if (e >= ETOT) return;
    int d = (e < EE) ? ei[EE + e] : (e - EE);   // self loop for e >= EE
    atomicAdd(&g_deg[d], 1);
}

__global__ __launch_bounds__(256) void scan1_kernel() {
    int b = blockIdx.x;
    int i = b * 256 + threadIdx.x;
    int v = (i < NN) ? g_deg[i] : 0;
    int lane = threadIdx.x & 31, w = threadIdx.x >> 5;
    int s = v;
    #pragma unroll
    for (int off = 1; off < 32; off <<= 1) {
        int t = __shfl_up_sync(0xffffffffu, s, off);
        if (lane >= off) s += t;
    }
    __shared__ int ws[8];
    if (lane == 31) ws[w] = s;
    __syncthreads();
    if (threadIdx.x == 0) {
        int acc = 0;
        #pragma unroll
        for (int j = 0; j < 8; j++) { int t = ws[j]; ws[j] = acc; acc += t; }
        g_blocksum[b] = acc;
    }
    __syncthreads();
    s += ws[w];
    if (i < NN) g_rowptr[i + 1] = s;
}

__global__ __launch_bounds__(256) void scan2_kernel() {
    int t = threadIdx.x;
    int v = (t < NBLK) ? g_blocksum[t] : 0;
    int lane = t & 31, w = t >> 5;
    int s = v;
    #pragma unroll
    for (int off = 1; off < 32; off <<= 1) {
        int u = __shfl_up_sync(0xffffffffu, s, off);
        if (lane >= off) s += u;
    }
    __shared__ int ws[8];
    if (lane == 31) ws[w] = s;
    __syncthreads();
    if (t == 0) {
        int acc = 0;
        #pragma unroll
        for (int j = 0; j < 8; j++) { int u = ws[j]; ws[j] = acc; acc += u; }
    }
    __syncthreads();
    s += ws[w];
    g_blockoff[t] = s - v;
}

__global__ void scan3_kernel() {
    int i = blockIdx.x * blockDim.x + threadIdx.x;
    if (i >= NN) return;
    int off  = g_blockoff[i >> 8];
    int incl = g_rowptr[i + 1] + off;
    g_rowptr[i + 1] = incl;
    g_cursor[i]     = incl - g_deg[i];
    if (i == 0) g_rowptr[0] = 0;
}

__global__ void scatter_edges_kernel(const int* __restrict__ ei) {
    int e = blockIdx.x * blockDim.x + threadIdx.x;
    if (e >= ETOT) return;
    int s, d;
    if (e < EE) { s = ei[e]; d = ei[EE + e]; }
    else        { s = d = e - EE; }
    int pos = atomicAdd(&g_cursor[d], 1);
    g_csr[pos] = s;
}

// ---------------- fp32 -> fp16 input conversion (one kernel) ----------------
__global__ __launch_bounds__(256) void convert_inputs_kernel(
    const float* __restrict__ x, const float* __restrict__ W1,
    const float* __restrict__ W2, const float* __restrict__ Wf)
{
    int i = blockIdx.x * blockDim.x + threadIdx.x;   // float4 index for x
    if (i < NN * FIN / 4) {
        float4 v = *(const float4*)(x + i * 4);
        __half2* p = (__half2*)(g_xh + i * 4);
        p[0] = __floats2half2_rn(v.x, v.y);
        p[1] = __floats2half2_rn(v.z, v.w);
    }
    if (i < FIN * CH1 / 4) {
        float4 v = *(const float4*)(W1 + i * 4);
        __half2* p = (__half2*)(g_W1h + i * 4);
        p[0] = __floats2half2_rn(v.x, v.y);
        p[1] = __floats2half2_rn(v.z, v.w);
    }
    if (i < CH1 * CH2 / 4) {
        float4 v = *(const float4*)(W2 + i * 4);
        __half2* p = (__half2*)(g_W2h + i * 4);
        p[0] = __floats2half2_rn(v.x, v.y);
        p[1] = __floats2half2_rn(v.z, v.w);
    }
    if (i < CH2 * 128) {
        int r = i >> 7, cc = i & 127;
        g_Wfh[i] = __float2half((cc < NCLS) ? Wf[r * NCLS + cc] : 0.f);
    }
}

// ---------------- fp16 tensor-core GEMM: 256x128 tile, 4-stage cp.async -----
// C[M,ncols] = A[M,K] @ B[K,N] (+bias). A,B fp16 in gmem. N mult of 128,
// K mult of 32 (KT = K/32 >= 4). 8 warps as 4x2 -> warp tile 64x64.
// One __syncthreads per K-iteration; 3 tile-loads in flight during compute.
// HPB: heads per 128-col tile for fused attn-coef epilogue (0 = none).
// HALFOUT: C written fp16; else fp32 + bias.
#define SAH 40     // A smem row stride (halfs): 80 B, ldmatrix conflict-free
#define SBH 136    // B smem row stride (halfs): 272 B, conflict-free
#define A_BUF (256 * SAH)
#define B_BUF (32 * SBH)
#define STAGES 4
#define GEMM_SMEM ((STAGES * (A_BUF + B_BUF)) * 2)   // 116736 bytes

__device__ __forceinline__ void ldm_x4(uint32_t* r, uint32_t addr) {
    asm volatile("ldmatrix.sync.aligned.m8n8.x4.shared.b16 {%0,%1,%2,%3}, [%4];"
                 : "=r"(r[0]), "=r"(r[1]), "=r"(r[2]), "=r"(r[3]) : "r"(addr));
}
__device__ __forceinline__ void ldm_x4_t(uint32_t* r, uint32_t addr) {
    asm volatile("ldmatrix.sync.aligned.m8n8.x4.trans.shared.b16 {%0,%1,%2,%3}, [%4];"
                 : "=r"(r[0]), "=r"(r[1]), "=r"(r[2]), "=r"(r[3]) : "r"(addr));
}
__device__ __forceinline__ void mma_f16(float* c, uint32_t a0, uint32_t a1,
                                        uint32_t a2, uint32_t a3,
                                        uint32_t b0, uint32_t b1) {
    asm volatile(
        "mma.sync.aligned.m16n8k16.row.col.f32.f16.f16.f32 "
        "{%0,%1,%2,%3},{%4,%5,%6,%7},{%8,%9},{%0,%1,%2,%3};\n"
        : "+f"(c[0]), "+f"(c[1]), "+f"(c[2]), "+f"(c[3])
        : "r"(a0), "r"(a1), "r"(a2), "r"(a3), "r"(b0), "r"(b1));
}
__device__ __forceinline__ void cp16(uint32_t dst, const void* src, bool ok) {
    int sz = ok ? 16 : 0;
    asm volatile("cp.async.ca.shared.global [%0], [%1], 16, %2;"
                 :: "r"(dst), "l"(src), "r"(sz));
}

template <int HPB, bool HALFOUT>
__global__ __launch_bounds__(256) void gemm_f16_kernel(
    int M, int N, int K,
    const __half* __restrict__ A, const __half* __restrict__ B,
    float* __restrict__ Cf, __half* __restrict__ Chalf,
    int ldc, int ncols, const float* __restrict__ bias,
    const float* __restrict__ avs, const float* __restrict__ avd,
    float* __restrict__ o_src, float* __restrict__ o_dst)
{
    extern __shared__ __half smem[];
    uint32_t smem_u32 = (uint32_t)__cvta_generic_to_shared(smem);

    int tid  = threadIdx.x;
    int row0 = blockIdx.y * 256;
    int col0 = blockIdx.x * 128;
    int warp = tid >> 5, lane = tid & 31;
    int wm = warp >> 1, wn = warp & 1;       // 4x2 warps -> warp tile 64x64
    int tg = lane >> 2, tig = lane & 3;

    bool aok = (row0 + tid) < M;

    auto issue = [&](int kt) {
        int buf = kt & (STAGES - 1);
        // A: row = tid, 4 x 16B chunks
        const __half* asrc = A + (size_t)(row0 + tid) * K + kt * 32;
        uint32_t adst = smem_u32 + (uint32_t)((buf * A_BUF + tid * SAH) * 2);
        #pragma unroll
        for (int i = 0; i < 4; i++)
            cp16(adst + i * 16, asrc + i * 8, aok);
        // B: row = tid>>3, 2 x 16B chunks
        int brow = tid >> 3, bch = (tid & 7) * 2;
        const __half* bsrc = B + (size_t)(kt * 32 + brow) * N + col0 + bch * 8;
        uint32_t bdst = smem_u32 +
            (uint32_t)((STAGES * A_BUF + buf * B_BUF + brow * SBH + bch * 8) * 2);
        cp16(bdst,      bsrc,     true);
        cp16(bdst + 16, bsrc + 8, true);
        asm volatile("cp.async.commit_group;");
    };

    float c[4][8][4];
    #pragma unroll
    for (int mi = 0; mi < 4; mi++)
        #pragma unroll
        for (int ni = 0; ni < 8; ni++)
            #pragma unroll
            for (int j = 0; j < 4; j++) c[mi][ni][j] = 0.0f;

    int la = lane & 15, lh = lane >> 4;
    uint32_t a_lane = (uint32_t)((la * SAH + lh * 8) * 2);
    uint32_t b_lane = (uint32_t)((la * SBH + lh * 8) * 2);

    auto compute = [&](int buf) {
        uint32_t sa = smem_u32 + (uint32_t)(buf * A_BUF * 2) + a_lane
                    + (uint32_t)(wm * 64 * SAH * 2);
        uint32_t sb = smem_u32 + (uint32_t)((STAGES * A_BUF + buf * B_BUF) * 2) + b_lane
                    + (uint32_t)(wn * 64 * 2);
        #pragma unroll
        for (int ks = 0; ks < 2; ks++) {
            int kk = ks * 16;
            uint32_t af[4][4], bf[4][4];
            #pragma unroll
            for (int mi = 0; mi < 4; mi++)
                ldm_x4(af[mi], sa + (uint32_t)((mi * 16 * SAH + kk) * 2));
            #pragma unroll
            for (int np = 0; np < 4; np++)
                ldm_x4_t(bf[np], sb + (uint32_t)((kk * SBH + np * 16) * 2));
            #pragma unroll
            for (int mi = 0; mi < 4; mi++)
                #pragma unroll
                for (int np = 0; np < 4; np++) {
                    mma_f16(c[mi][np * 2],     af[mi][0], af[mi][1], af[mi][2], af[mi][3],
                            bf[np][0], bf[np][1]);
                    mma_f16(c[mi][np * 2 + 1], af[mi][0], af[mi][1], af[mi][2], af[mi][3],
                            bf[np][2], bf[np][3]);
                }
        }
    };

    int KT = K / 32;    // >= 4 for all our shapes (8, 16, 8)
    // prologue: 3 stages in flight, stage 0 ready
    issue(0); issue(1); issue(2);
    asm volatile("cp.async.wait_group 2;");
    __syncthreads();

    for (int kt = 0; kt < KT; kt++) {
        compute(kt & (STAGES - 1));
        if (kt + 3 < KT) {
            issue(kt + 3);
            asm volatile("cp.async.wait_group 2;");   // stage kt+1 ready
        } else {
            asm volatile("cp.async.wait_group 0;");
        }
        __syncthreads();
    }

    // ---- fused attention-coefficient epilogue (overlay dead smem) ----
    if (HPB > 0) {
        float* sm_src = (float*)smem;          // [2][256]
        float* sm_dst = sm_src + 512;          // [2][256]
        float sa_[4][2], da_[4][2];
        #pragma unroll
        for (int mi = 0; mi < 4; mi++) {
            sa_[mi][0] = sa_[mi][1] = 0.f;
            da_[mi][0] = da_[mi][1] = 0.f;
        }
        #pragma unroll
        for (int ni = 0; ni < 8; ni++) {
            int cl = wn * 64 + ni * 8 + tig * 2;
            float ws0 = avs[col0 + cl], ws1 = avs[col0 + cl + 1];
            float wd0 = avd[col0 + cl], wd1 = avd[col0 + cl + 1];
            #pragma unroll
            for (int mi = 0; mi < 4; mi++) {
                sa_[mi][0] += c[mi][ni][0] * ws0 + c[mi][ni][1] * ws1;
                da_[mi][0] += c[mi][ni][0] * wd0 + c[mi][ni][1] * wd1;
                sa_[mi][1] += c[mi][ni][2] * ws0 + c[mi][ni][3] * ws1;
                da_[mi][1] += c[mi][ni][2] * wd0 + c[mi][ni][3] * wd1;
            }
        }
        #pragma unroll
        for (int mi = 0; mi < 4; mi++)
            #pragma unroll
            for (int p = 0; p < 2; p++) {
                sa_[mi][p] += __shfl_xor_sync(0xffffffffu, sa_[mi][p], 1);
                sa_[mi][p] += __shfl_xor_sync(0xffffffffu, sa_[mi][p], 2);
                da_[mi][p] += __shfl_xor_sync(0xffffffffu, da_[mi][p], 1);
                da_[mi][p] += __shfl_xor_sync(0xffffffffu, da_[mi][p], 2);
            }
        if (tig == 0) {
            #pragma unroll
            for (int mi = 0; mi < 4; mi++) {
                int rl = wm * 64 + mi * 16 + tg;
                sm_src[wn * 256 + rl]     = sa_[mi][0];
                sm_src[wn * 256 + rl + 8] = sa_[mi][1];
                sm_dst[wn * 256 + rl]     = da_[mi][0];
                sm_dst[wn * 256 + rl + 8] = da_[mi][1];
            }
        }
        __syncthreads();
        {
            int r = row0 + tid;
            if (r < M) {
                if (HPB == 1) {
                    o_src[r * HH + blockIdx.x] = sm_src[tid] + sm_src[256 + tid];
                    o_dst[r * HH + blockIdx.x] = sm_dst[tid] + sm_dst[256 + tid];
                } else {
                    int hb = blockIdx.x * 2;
                    o_src[r * HH + hb]     = sm_src[tid];
                    o_src[r * HH + hb + 1] = sm_src[256 + tid];
                    o_dst[r * HH + hb]     = sm_dst[tid];
                    o_dst[r * HH + hb + 1] = sm_dst[256 + tid];
                }
            }
        }
    }

    // ---- C write ----
    #pragma unroll
    for (int mi = 0; mi < 4; mi++) {
        int r = row0 + wm * 64 + mi * 16 + tg;
        #pragma unroll
        for (int ni = 0; ni < 8; ni++) {
            int cc = col0 + wn * 64 + ni * 8 + tig * 2;
            if (cc >= ncols) continue;
            if (HALFOUT) {
                if (r < M)
                    *(__half2*)(Chalf + (size_t)r * ldc + cc) =
                        __floats2half2_rn(c[mi][ni][0], c[mi][ni][1]);
                if (r + 8 < M)
                    *(__half2*)(Chalf + (size_t)(r + 8) * ldc + cc) =
                        __floats2half2_rn(c[mi][ni][2], c[mi][ni][3]);
            } else {
                float b0 = bias ? bias[cc]     : 0.f;
                float b1 = bias ? bias[cc + 1] : 0.f;
                if (r < M) {
                    Cf[(size_t)r * ldc + cc]     = c[mi][ni][0] + b0;
                    Cf[(size_t)r * ldc + cc + 1] = c[mi][ni][1] + b1;
                }
                if (r + 8 < M) {
                    Cf[(size_t)(r + 8) * ldc + cc]     = c[mi][ni][2] + b0;
                    Cf[(size_t)(r + 8) * ldc + cc + 1] = c[mi][ni][3] + b1;
                }
            }
        }
    }
}

// ---------------- GAT softmax + aggregation (one block per dst node) --------
// out (fp16) = elu( softmax-weighted sum of fp16 messages + bias )
#define DCAP 512
template <int CH>
__global__ __launch_bounds__(128) void gat_agg_kernel(
    const __half* __restrict__ h,
    const float* __restrict__ asrc, const float* __restrict__ adst,
    const float* __restrict__ bias, __half* __restrict__ out)
{
    constexpr int VEC = CH / 128;             // 4 (layer1) or 2 (layer2)
    __shared__ int   ssrc[DCAP];
    __shared__ float sexp[DCAP * HH];
    __shared__ float red[4][HH];

    int d    = blockIdx.x;
    int tid  = threadIdx.x;
    int lane = tid & 31, warp = tid >> 5;
    int s0   = g_rowptr[d];
    int deg  = g_rowptr[d + 1] - s0;

    float4 ad4 = *(const float4*)&adst[d * HH];

    float sm[HH] = {0.f, 0.f, 0.f, 0.f};
    if (deg <= DCAP) {
        for (int j = tid; j < deg; j += 128) {
            int s = g_csr[s0 + j];
            ssrc[j] = s;
            float4 a = *(const float4*)&asrc[s * HH];
            float e0 = a.x + ad4.x; e0 = (e0 > 0.f) ? e0 : SLOPE * e0; e0 = __expf(e0);
            float e1 = a.y + ad4.y; e1 = (e1 > 0.f) ? e1 : SLOPE * e1; e1 = __expf(e1);
            float e2 = a.z + ad4.z; e2 = (e2 > 0.f) ? e2 : SLOPE * e2; e2 = __expf(e2);
            float e3 = a.w + ad4.w; e3 = (e3 > 0.f) ? e3 : SLOPE * e3; e3 = __expf(e3);
            sexp[j * HH + 0] = e0; sexp[j * HH + 1] = e1;
            sexp[j * HH + 2] = e2; sexp[j * HH + 3] = e3;
            sm[0] += e0; sm[1] += e1; sm[2] += e2; sm[3] += e3;
        }
    } else {
        for (int j = tid; j < deg; j += 128) {
            int s = g_csr[s0 + j];
            float4 a = *(const float4*)&asrc[s * HH];
            float e0 = a.x + ad4.x; e0 = (e0 > 0.f) ? e0 : SLOPE * e0;
            float e1 = a.y + ad4.y; e1 = (e1 > 0.f) ? e1 : SLOPE * e1;
            float e2 = a.z + ad4.z; e2 = (e2 > 0.f) ? e2 : SLOPE * e2;
            float e3 = a.w + ad4.w; e3 = (e3 > 0.f) ? e3 : SLOPE * e3;
            sm[0] += __expf(e0); sm[1] += __expf(e1);
            sm[2] += __expf(e2); sm[3] += __expf(e3);
        }
    }
    #pragma unroll
    for (int hh = 0; hh < HH; hh++)
        #pragma unroll
        for (int off = 16; off > 0; off >>= 1)
            sm[hh] += __shfl_xor_sync(0xffffffffu, sm[hh], off);
    if (lane == 0)
        #pragma unroll
        for (int hh = 0; hh < HH; hh++) red[warp][hh] = sm[hh];
    __syncthreads();   // also publishes ssrc/sexp

    int head = tid >> 5;
    float ih = 1.0f / (red[0][head] + red[1][head] + red[2][head] + red[3][head] + 1e-16f);

    float acc[VEC];
    #pragma unroll
    for (int j = 0; j < VEC; j++) acc[j] = 0.f;

    const int hoff = tid * (VEC / 2);   // __half2 offset within row

    if (deg <= DCAP) {
        int j = 0;
        for (; j + 4 <= deg; j += 4) {
            int sA = ssrc[j], sB = ssrc[j + 1], sC = ssrc[j + 2], sD = ssrc[j + 3];
            float eA = sexp[(j    ) * HH + head];
            float eB = sexp[(j + 1) * HH + head];
            float eC = sexp[(j + 2) * HH + head];
            float eD = sexp[(j + 3) * HH + head];
            const __half2* pA = (const __half2*)(h + (size_t)sA * CH) + hoff;
            const __half2* pB = (const __half2*)(h + (size_t)sB * CH) + hoff;
            const __half2* pC = (const __half2*)(h + (size_t)sC * CH) + hoff;
            const __half2* pD = (const __half2*)(h + (size_t)sD * CH) + hoff;
            if (VEC == 4) {
                __half2 a0 = pA[0], a1 = pA[1];
                __half2 b0 = pB[0], b1 = pB[1];
                __half2 c0 = pC[0], c1 = pC[1];
                __half2 d0 = pD[0], d1 = pD[1];
                float2 f;
                f = __half22float2(a0); acc[0] += eA * f.x; acc[1] += eA * f.y;
                f = __half22float2(a1); acc[2] += eA * f.x; acc[3] += eA * f.y;
                f = __half22float2(b0); acc[0] += eB * f.x; acc[1] += eB * f.y;
                f = __half22float2(b1); acc[2] += eB * f.x; acc[3] += eB * f.y;
                f = __half22float2(c0); acc[0] += eC * f.x; acc[1] += eC * f.y;
                f = __half22float2(c1); acc[2] += eC * f.x; acc[3] += eC * f.y;
                f = __half22float2(d0); acc[0] += eD * f.x; acc[1] += eD * f.y;
                f = __half22float2(d1); acc[2] += eD * f.x; acc[3] += eD * f.y;
            } else {
                __half2 a0 = pA[0], b0 = pB[0], c0 = pC[0], d0 = pD[0];
                float2 f;
                f = __half22float2(a0); acc[0] += eA * f.x; acc[1] += eA * f.y;
                f = __half22float2(b0); acc[0] += eB * f.x; acc[1] += eB * f.y;
                f = __half22float2(c0); acc[0] += eC * f.x; acc[1] += eC * f.y;
                f = __half22float2(d0); acc[0] += eD * f.x; acc[1] += eD * f.y;
            }
        }
        for (; j < deg; j++) {
            int s = ssrc[j];
            float e = sexp[j * HH + head];
            const __half2* p = (const __half2*)(h + (size_t)s * CH) + hoff;
            #pragma unroll
            for (int q = 0; q < VEC / 2; q++) {
                float2 f = __half22float2(p[q]);
                acc[q * 2]     += e * f.x;
                acc[q * 2 + 1] += e * f.y;
            }
        }
    } else {
        for (int c0 = 0; c0 < deg; c0 += DCAP) {
            int cn = min(DCAP, deg - c0);
            __syncthreads();
            for (int j = tid; j < cn; j += 128) {
                int s = g_csr[s0 + c0 + j];
                ssrc[j] = s;
                float4 a = *(const float4*)&asrc[s * HH];
                float e0 = a.x + ad4.x; e0 = (e0 > 0.f) ? e0 : SLOPE * e0;
                float e1 = a.y + ad4.y; e1 = (e1 > 0.f) ? e1 : SLOPE * e1;
                float e2 = a.z + ad4.z; e2 = (e2 > 0.f) ? e2 : SLOPE * e2;
                float e3 = a.w + ad4.w; e3 = (e3 > 0.f) ? e3 : SLOPE * e3;
                sexp[j * HH + 0] = __expf(e0); sexp[j * HH + 1] = __expf(e1);
                sexp[j * HH + 2] = __expf(e2); sexp[j * HH + 3] = __expf(e3);
            }
            __syncthreads();
            for (int j = 0; j < cn; j++) {
                int s = ssrc[j];
                float e = sexp[j * HH + head];
                const __half2* p = (const __half2*)(h + (size_t)s * CH) + hoff;
                #pragma unroll
                for (int q = 0; q < VEC / 2; q++) {
                    float2 f = __half22float2(p[q]);
                    acc[q * 2]     += e * f.x;
                    acc[q * 2 + 1] += e * f.y;
                }
            }
        }
    }

    // elu + bias, write fp16
    float v0 = acc[0] * ih + bias[tid * VEC + 0];
    float v1 = acc[1] * ih + bias[tid * VEC + 1];
    v0 = (v0 > 0.f) ? v0 : expm1f(v0);
    v1 = (v1 > 0.f) ? v1 : expm1f(v1);
    __half2* op = (__half2*)(out + (size_t)d * CH + tid * VEC);
    op[0] = __floats2half2_rn(v0, v1);
    if (VEC == 4) {
        float v2 = acc[2] * ih + bias[tid * VEC + 2];
        float v3 = acc[3] * ih + bias[tid * VEC + 3];
        v2 = (v2 > 0.f) ? v2 : expm1f(v2);
        v3 = (v3 > 0.f) ? v3 : expm1f(v3);
        op[1] = __floats2half2_rn(v2, v3);
    }
}

// ---------------- launch ----------------------------------------------------
extern "C" void kernel_launch(void* const* d_in, const int* in_sizes, int n_in,
                              void* d_out, int out_size)
{
    const float* x   = (const float*)d_in[0];
    const int*   ei  = (const int*)  d_in[1];
    const float* W1  = (const float*)d_in[2];
    const float* as1 = (const float*)d_in[3];
    const float* ad1 = (const float*)d_in[4];
    const float* b1  = (const float*)d_in[5];
    const float* W2  = (const float*)d_in[6];
    const float* as2 = (const float*)d_in[7];
    const float* ad2 = (const float*)d_in[8];
    const float* b2  = (const float*)d_in[9];
    const float* Wf  = (const float*)d_in[10];
    const float* bf  = (const float*)d_in[11];
    float* out = (float*)d_out;

    __half *xh, *W1h, *W2h, *Wfh, *h1h, *h2h, *g1h, *g2h;
    float *pas, *pad;
    cudaGetSymbolAddress((void**)&xh,  g_xh);
    cudaGetSymbolAddress((void**)&W1h, g_W1h);
    cudaGetSymbolAddress((void**)&W2h, g_W2h);
    cudaGetSymbolAddress((void**)&Wfh, g_Wfh);
    cudaGetSymbolAddress((void**)&h1h, g_h1h);
    cudaGetSymbolAddress((void**)&h2h, g_h2h);
    cudaGetSymbolAddress((void**)&g1h, g_g1h);
    cudaGetSymbolAddress((void**)&g2h, g_g2h);
    cudaGetSymbolAddress((void**)&pas, g_asrc);
    cudaGetSymbolAddress((void**)&pad, g_adst);

    cudaFuncSetAttribute(gemm_f16_kernel<1, true>,
                         cudaFuncAttributeMaxDynamicSharedMemorySize, GEMM_SMEM);
    cudaFuncSetAttribute(gemm_f16_kernel<2, true>,
                         cudaFuncAttributeMaxDynamicSharedMemorySize, GEMM_SMEM);
    cudaFuncSetAttribute(gemm_f16_kernel<0, false>,
                         cudaFuncAttributeMaxDynamicSharedMemorySize, GEMM_SMEM);

    int grid_y = (NN + 255) / 256;   // 196

    // Launch order keeps GEMM1 as the 4th launch (ncu fixed-skip capture).
    zero_deg_kernel<<<(NN + 255) / 256, 256>>>();
    count_deg_kernel<<<(ETOT + 255) / 256, 256>>>(ei);
    convert_inputs_kernel<<<(NN * FIN / 4 + 255) / 256, 256>>>(x, W1, W2, Wf);

    // Layer 1 GEMM (+ fused attn coefs, fp16 h out)
    gemm_f16_kernel<1, true><<<dim3(CH1 / 128, grid_y), 256, GEMM_SMEM>>>(
        NN, CH1, FIN, xh, W1h, (float*)nullptr, h1h, CH1, CH1, (const float*)nullptr,
        as1, ad1, pas, pad);

    // CSR build
    scan1_kernel<<<NBLK, 256>>>();
    scan2_kernel<<<1, 256>>>();
    scan3_kernel<<<NBLK, 256>>>();
    scatter_edges_kernel<<<(ETOT + 255) / 256, 256>>>(ei);

    gat_agg_kernel<CH1><<<NN, 128>>>(h1h, pas, pad, b1, g1h);

    // Layer 2
    gemm_f16_kernel<2, true><<<dim3(CH2 / 128, grid_y), 256, GEMM_SMEM>>>(
        NN, CH2, CH1, g1h, W2h, (float*)nullptr, h2h, CH2, CH2, (const float*)nullptr,
        as2, ad2, pas, pad);
    gat_agg_kernel<CH2><<<NN, 128>>>(h2h, pas, pad, b2, g2h);

    // Final classifier: out[N,50] = g2 @ Wfpad + bf
    gemm_f16_kernel<0, false><<<dim3(1, grid_y), 256, GEMM_SMEM>>>(
        NN, 128, CH2, g2h, Wfh, out, (__half*)nullptr, NCLS, NCLS, bf,
        (const float*)nullptr, (const float*)nullptr,
        (float*)nullptr, (float*)nullptr);
}

// round 11
// speedup vs baseline: 1.3288x; 1.3288x over previous
#include <cuda_runtime.h>
#include <cuda_fp16.h>
#include <math.h>
#include <stdint.h>

// Problem constants (fixed by the dataset)
#define NN    50000
#define EE    800000
#define ETOT  850000        // EE + NN self loops
#define FIN   256
#define HH    4
#define CC1   128
#define CC2   64
#define CH1   512           // HH*CC1
#define CH2   256           // HH*CC2
#define NCLS  50
#define SLOPE 0.2f
#define NBLK  ((NN + 255) / 256)

// ---------------- scratch (device globals; no allocations allowed) ----------
__device__ __half g_xh [NN * FIN];    // x   in fp16 (GEMM1 A)
__device__ __half g_W1h[FIN * CH1];   // W1  fp16
__device__ __half g_W2h[CH1 * CH2];   // W2  fp16
__device__ __half g_Wfh[CH2 * 128];   // Wf  fp16, zero-padded to 128 cols
__device__ __half g_h1h[NN * CH1];    // x @ W1  (messages, fp16)
__device__ __half g_h2h[NN * CH2];    // g1 @ W2 (messages, fp16)
__device__ __half g_g1h[NN * CH1];    // elu(agg1 + b1), fp16 (GEMM2 A)
__device__ __half g_g2h[NN * CH2];    // elu(agg2 + b2), fp16 (GEMM3 A)
__device__ float g_asrc[NN * HH];
__device__ float g_adst[NN * HH];
__device__ int   g_deg[NN];
__device__ int   g_rowptr[NN + 1];
__device__ int   g_cursor[NN];
__device__ int   g_csr[ETOT];
__device__ int   g_blocksum[256];
__device__ int   g_blockoff[256];

// ---------------- CSR construction ------------------------------------------
__global__ void zero_deg_kernel() {
    int i = blockIdx.x * blockDim.x + threadIdx.x;
    if (i < NN) g_deg[i] = 0;
}

__global__ void count_deg_kernel(const int* __restrict__ ei) {
    int e = blockIdx.x * blockDim.x + threadIdx.x;
    if (e >= ETOT) return;
    int d = (e < EE) ? ei[EE + e] : (e - EE);   // self loop for e >= EE
    atomicAdd(&g_deg[d], 1);
}

__global__ __launch_bounds__(256) void scan1_kernel() {
    int b = blockIdx.x;
    int i = b * 256 + threadIdx.x;
    int v = (i < NN) ? g_deg[i] : 0;
    int lane = threadIdx.x & 31, w = threadIdx.x >> 5;
    int s = v;
    #pragma unroll
    for (int off = 1; off < 32; off <<= 1) {
        int t = __shfl_up_sync(0xffffffffu, s, off);
        if (lane >= off) s += t;
    }
    __shared__ int ws[8];
    if (lane == 31) ws[w] = s;
    __syncthreads();
    if (threadIdx.x == 0) {
        int acc = 0;
        #pragma unroll
        for (int j = 0; j < 8; j++) { int t = ws[j]; ws[j] = acc; acc += t; }
        g_blocksum[b] = acc;
    }
    __syncthreads();
    s += ws[w];
    if (i < NN) g_rowptr[i + 1] = s;
}

__global__ __launch_bounds__(256) void scan2_kernel() {
    int t = threadIdx.x;
    int v = (t < NBLK) ? g_blocksum[t] : 0;
    int lane = t & 31, w = t >> 5;
    int s = v;
    #pragma unroll
    for (int off = 1; off < 32; off <<= 1) {
        int u = __shfl_up_sync(0xffffffffu, s, off);
        if (lane >= off) s += u;
    }
    __shared__ int ws[8];
    if (lane == 31) ws[w] = s;
    __syncthreads();
    if (t == 0) {
        int acc = 0;
        #pragma unroll
        for (int j = 0; j < 8; j++) { int u = ws[j]; ws[j] = acc; acc += u; }
    }
    __syncthreads();
    s += ws[w];
    g_blockoff[t] = s - v;
}

__global__ void scan3_kernel() {
    int i = blockIdx.x * blockDim.x + threadIdx.x;
    if (i >= NN) return;
    int off  = g_blockoff[i >> 8];
    int incl = g_rowptr[i + 1] + off;
    g_rowptr[i + 1] = incl;
    g_cursor[i]     = incl - g_deg[i];
    if (i == 0) g_rowptr[0] = 0;
}

__global__ void scatter_edges_kernel(const int* __restrict__ ei) {
    int e = blockIdx.x * blockDim.x + threadIdx.x;
    if (e >= ETOT) return;
    int s, d;
    if (e < EE) { s = ei[e]; d = ei[EE + e]; }
    else        { s = d = e - EE; }
    int pos = atomicAdd(&g_cursor[d], 1);
    g_csr[pos] = s;
}

// ---------------- fp32 -> fp16 input conversion (one kernel) ----------------
__global__ __launch_bounds__(256) void convert_inputs_kernel(
    const float* __restrict__ x, const float* __restrict__ W1,
    const float* __restrict__ W2, const float* __restrict__ Wf)
{
    int i = blockIdx.x * blockDim.x + threadIdx.x;   // float4 index for x
    if (i < NN * FIN / 4) {
        float4 v = *(const float4*)(x + i * 4);
        __half2* p = (__half2*)(g_xh + i * 4);
        p[0] = __floats2half2_rn(v.x, v.y);
        p[1] = __floats2half2_rn(v.z, v.w);
    }
    if (i < FIN * CH1 / 4) {
        float4 v = *(const float4*)(W1 + i * 4);
        __half2* p = (__half2*)(g_W1h + i * 4);
        p[0] = __floats2half2_rn(v.x, v.y);
        p[1] = __floats2half2_rn(v.z, v.w);
    }
    if (i < CH1 * CH2 / 4) {
        float4 v = *(const float4*)(W2 + i * 4);
        __half2* p = (__half2*)(g_W2h + i * 4);
        p[0] = __floats2half2_rn(v.x, v.y);
        p[1] = __floats2half2_rn(v.z, v.w);
    }
    if (i < CH2 * 128) {
        int r = i >> 7, cc = i & 127;
        g_Wfh[i] = __float2half((cc < NCLS) ? Wf[r * NCLS + cc] : 0.f);
    }
}

// ---------------- fp16 tensor-core GEMM: 256x128 tile, 2-stage cp.async -----
// (Exact R8 configuration: proven fastest. 4-stage variant regressed.)
#define SAH 40     // A smem row stride (halfs): 80 B, ldmatrix conflict-free
#define SBH 136    // B smem row stride (halfs): 272 B, conflict-free
#define A_BUF (256 * SAH)
#define B_BUF (32 * SBH)
#define GEMM_SMEM ((2 * A_BUF + 2 * B_BUF) * 2)   // bytes = 58368

__device__ __forceinline__ void ldm_x4(uint32_t* r, uint32_t addr) {
    asm volatile("ldmatrix.sync.aligned.m8n8.x4.shared.b16 {%0,%1,%2,%3}, [%4];"
                 : "=r"(r[0]), "=r"(r[1]), "=r"(r[2]), "=r"(r[3]) : "r"(addr));
}
__device__ __forceinline__ void ldm_x4_t(uint32_t* r, uint32_t addr) {
    asm volatile("ldmatrix.sync.aligned.m8n8.x4.trans.shared.b16 {%0,%1,%2,%3}, [%4];"
                 : "=r"(r[0]), "=r"(r[1]), "=r"(r[2]), "=r"(r[3]) : "r"(addr));
}
__device__ __forceinline__ void mma_f16(float* c, uint32_t a0, uint32_t a1,
                                        uint32_t a2, uint32_t a3,
                                        uint32_t b0, uint32_t b1) {
    asm volatile(
        "mma.sync.aligned.m16n8k16.row.col.f32.f16.f16.f32 "
        "{%0,%1,%2,%3},{%4,%5,%6,%7},{%8,%9},{%0,%1,%2,%3};\n"
        : "+f"(c[0]), "+f"(c[1]), "+f"(c[2]), "+f"(c[3])
        : "r"(a0), "r"(a1), "r"(a2), "r"(a3), "r"(b0), "r"(b1));
}
__device__ __forceinline__ void cp16(uint32_t dst, const void* src, bool ok) {
    int sz = ok ? 16 : 0;
    asm volatile("cp.async.ca.shared.global [%0], [%1], 16, %2;"
                 :: "r"(dst), "l"(src), "r"(sz));
}

template <int HPB, bool HALFOUT>
__global__ __launch_bounds__(256) void gemm_f16_kernel(
    int M, int N, int K,
    const __half* __restrict__ A, const __half* __restrict__ B,
    float* __restrict__ Cf, __half* __restrict__ Chalf,
    int ldc, int ncols, const float* __restrict__ bias,
    const float* __restrict__ avs, const float* __restrict__ avd,
    float* __restrict__ o_src, float* __restrict__ o_dst)
{
    extern __shared__ __half smem[];
    uint32_t smem_u32 = (uint32_t)__cvta_generic_to_shared(smem);

    int tid  = threadIdx.x;
    int row0 = blockIdx.y * 256;
    int col0 = blockIdx.x * 128;
    int warp = tid >> 5, lane = tid & 31;
    int wm = warp >> 1, wn = warp & 1;       // 4x2 warps -> warp tile 64x64
    int tg = lane >> 2, tig = lane & 3;

    bool aok = (row0 + tid) < M;

    auto issue = [&](int kt, int buf) {
        const __half* asrc = A + (size_t)(row0 + tid) * K + kt * 32;
        uint32_t adst = smem_u32 + (uint32_t)((buf * A_BUF + tid * SAH) * 2);
        #pragma unroll
        for (int i = 0; i < 4; i++)
            cp16(adst + i * 16, asrc + i * 8, aok);
        int brow = tid >> 3, bch = (tid & 7) * 2;
        const __half* bsrc = B + (size_t)(kt * 32 + brow) * N + col0 + bch * 8;
        uint32_t bdst = smem_u32 +
            (uint32_t)((2 * A_BUF + buf * B_BUF + brow * SBH + bch * 8) * 2);
        cp16(bdst,      bsrc,     true);
        cp16(bdst + 16, bsrc + 8, true);
        asm volatile("cp.async.commit_group;");
    };

    float c[4][8][4];
    #pragma unroll
    for (int mi = 0; mi < 4; mi++)
        #pragma unroll
        for (int ni = 0; ni < 8; ni++)
            #pragma unroll
            for (int j = 0; j < 4; j++) c[mi][ni][j] = 0.0f;

    int la = lane & 15, lh = lane >> 4;
    uint32_t a_lane = (uint32_t)((la * SAH + lh * 8) * 2);
    uint32_t b_lane = (uint32_t)((la * SBH + lh * 8) * 2);

    auto compute = [&](int buf) {
        uint32_t sa = smem_u32 + (uint32_t)(buf * A_BUF * 2) + a_lane
                    + (uint32_t)(wm * 64 * SAH * 2);
        uint32_t sb = smem_u32 + (uint32_t)((2 * A_BUF + buf * B_BUF) * 2) + b_lane
                    + (uint32_t)(wn * 64 * 2);
        #pragma unroll
        for (int ks = 0; ks < 2; ks++) {
            int kk = ks * 16;
            uint32_t af[4][4], bf[4][4];
            #pragma unroll
            for (int mi = 0; mi < 4; mi++)
                ldm_x4(af[mi], sa + (uint32_t)((mi * 16 * SAH + kk) * 2));
            #pragma unroll
            for (int np = 0; np < 4; np++)
                ldm_x4_t(bf[np], sb + (uint32_t)((kk * SBH + np * 16) * 2));
            #pragma unroll
            for (int mi = 0; mi < 4; mi++)
                #pragma unroll
                for (int np = 0; np < 4; np++) {
                    mma_f16(c[mi][np * 2],     af[mi][0], af[mi][1], af[mi][2], af[mi][3],
                            bf[np][0], bf[np][1]);
                    mma_f16(c[mi][np * 2 + 1], af[mi][0], af[mi][1], af[mi][2], af[mi][3],
                            bf[np][2], bf[np][3]);
                }
        }
    };

    int KT = K / 32;
    issue(0, 0);
    for (int kt = 0; kt < KT; kt++) {
        int buf = kt & 1;
        if (kt + 1 < KT) {
            issue(kt + 1, buf ^ 1);
            asm volatile("cp.async.wait_group 1;");
        } else {
            asm volatile("cp.async.wait_group 0;");
        }
        __syncthreads();
        compute(buf);
        __syncthreads();
    }

    // ---- fused attention-coefficient epilogue (overlay dead smem) ----
    if (HPB > 0) {
        float* sm_src = (float*)smem;          // [2][256]
        float* sm_dst = sm_src + 512;          // [2][256]
        float sa_[4][2], da_[4][2];
        #pragma unroll
        for (int mi = 0; mi < 4; mi++) {
            sa_[mi][0] = sa_[mi][1] = 0.f;
            da_[mi][0] = da_[mi][1] = 0.f;
        }
        #pragma unroll
        for (int ni = 0; ni < 8; ni++) {
            int cl = wn * 64 + ni * 8 + tig * 2;
            float ws0 = avs[col0 + cl], ws1 = avs[col0 + cl + 1];
            float wd0 = avd[col0 + cl], wd1 = avd[col0 + cl + 1];
            #pragma unroll
            for (int mi = 0; mi < 4; mi++) {
                sa_[mi][0] += c[mi][ni][0] * ws0 + c[mi][ni][1] * ws1;
                da_[mi][0] += c[mi][ni][0] * wd0 + c[mi][ni][1] * wd1;
                sa_[mi][1] += c[mi][ni][2] * ws0 + c[mi][ni][3] * ws1;
                da_[mi][1] += c[mi][ni][2] * wd0 + c[mi][ni][3] * wd1;
            }
        }
        #pragma unroll
        for (int mi = 0; mi < 4; mi++)
            #pragma unroll
            for (int p = 0; p < 2; p++) {
                sa_[mi][p] += __shfl_xor_sync(0xffffffffu, sa_[mi][p], 1);
                sa_[mi][p] += __shfl_xor_sync(0xffffffffu, sa_[mi][p], 2);
                da_[mi][p] += __shfl_xor_sync(0xffffffffu, da_[mi][p], 1);
                da_[mi][p] += __shfl_xor_sync(0xffffffffu, da_[mi][p], 2);
            }
        if (tig == 0) {
            #pragma unroll
            for (int mi = 0; mi < 4; mi++) {
                int rl = wm * 64 + mi * 16 + tg;
                sm_src[wn * 256 + rl]     = sa_[mi][0];
                sm_src[wn * 256 + rl + 8] = sa_[mi][1];
                sm_dst[wn * 256 + rl]     = da_[mi][0];
                sm_dst[wn * 256 + rl + 8] = da_[mi][1];
            }
        }
        __syncthreads();
        {
            int r = row0 + tid;
            if (r < M) {
                if (HPB == 1) {
                    o_src[r * HH + blockIdx.x] = sm_src[tid] + sm_src[256 + tid];
                    o_dst[r * HH + blockIdx.x] = sm_dst[tid] + sm_dst[256 + tid];
                } else {
                    int hb = blockIdx.x * 2;
                    o_src[r * HH + hb]     = sm_src[tid];
                    o_src[r * HH + hb + 1] = sm_src[256 + tid];
                    o_dst[r * HH + hb]     = sm_dst[tid];
                    o_dst[r * HH + hb + 1] = sm_dst[256 + tid];
                }
            }
        }
    }

    // ---- C write ----
    #pragma unroll
    for (int mi = 0; mi < 4; mi++) {
        int r = row0 + wm * 64 + mi * 16 + tg;
        #pragma unroll
        for (int ni = 0; ni < 8; ni++) {
            int cc = col0 + wn * 64 + ni * 8 + tig * 2;
            if (cc >= ncols) continue;
            if (HALFOUT) {
                if (r < M)
                    *(__half2*)(Chalf + (size_t)r * ldc + cc) =
                        __floats2half2_rn(c[mi][ni][0], c[mi][ni][1]);
                if (r + 8 < M)
                    *(__half2*)(Chalf + (size_t)(r + 8) * ldc + cc) =
                        __floats2half2_rn(c[mi][ni][2], c[mi][ni][3]);
            } else {
                float b0 = bias ? bias[cc]     : 0.f;
                float b1 = bias ? bias[cc + 1] : 0.f;
                if (r < M) {
                    Cf[(size_t)r * ldc + cc]     = c[mi][ni][0] + b0;
                    Cf[(size_t)r * ldc + cc + 1] = c[mi][ni][1] + b1;
                }
                if (r + 8 < M) {
                    Cf[(size_t)(r + 8) * ldc + cc]     = c[mi][ni][2] + b0;
                    Cf[(size_t)(r + 8) * ldc + cc + 1] = c[mi][ni][3] + b1;
                }
            }
        }
    }
}

// ---------------- GAT softmax + aggregation (one block per dst node) --------
// out (fp16) = elu( softmax-weighted sum of fp16 messages + bias ).
// THREADS=256 for layer 1 (8 warps, VEC=2) to hide gather latency;
// THREADS=128 for layer 2.
#define DCAP 512
template <int CH, int THREADS>
__global__ __launch_bounds__(THREADS) void gat_agg_kernel(
    const __half* __restrict__ h,
    const float* __restrict__ asrc, const float* __restrict__ adst,
    const float* __restrict__ bias, __half* __restrict__ out)
{
    constexpr int VEC = CH / THREADS;         // 2 for both instantiations
    constexpr int W   = THREADS / 32;
    __shared__ int   ssrc[DCAP];
    __shared__ float sexp[DCAP * HH];
    __shared__ float red[W][HH];

    int d    = blockIdx.x;
    int tid  = threadIdx.x;
    int lane = tid & 31, warp = tid >> 5;
    int s0   = g_rowptr[d];
    int deg  = g_rowptr[d + 1] - s0;

    float4 ad4 = *(const float4*)&adst[d * HH];

    float sm[HH] = {0.f, 0.f, 0.f, 0.f};
    if (deg <= DCAP) {
        for (int j = tid; j < deg; j += THREADS) {
            int s = g_csr[s0 + j];
            ssrc[j] = s;
            float4 a = *(const float4*)&asrc[s * HH];
            float e0 = a.x + ad4.x; e0 = (e0 > 0.f) ? e0 : SLOPE * e0; e0 = __expf(e0);
            float e1 = a.y + ad4.y; e1 = (e1 > 0.f) ? e1 : SLOPE * e1; e1 = __expf(e1);
            float e2 = a.z + ad4.z; e2 = (e2 > 0.f) ? e2 : SLOPE * e2; e2 = __expf(e2);
            float e3 = a.w + ad4.w; e3 = (e3 > 0.f) ? e3 : SLOPE * e3; e3 = __expf(e3);
            sexp[j * HH + 0] = e0; sexp[j * HH + 1] = e1;
            sexp[j * HH + 2] = e2; sexp[j * HH + 3] = e3;
            sm[0] += e0; sm[1] += e1; sm[2] += e2; sm[3] += e3;
        }
    } else {
        for (int j = tid; j < deg; j += THREADS) {
            int s = g_csr[s0 + j];
            float4 a = *(const float4*)&asrc[s * HH];
            float e0 = a.x + ad4.x; e0 = (e0 > 0.f) ? e0 : SLOPE * e0;
            float e1 = a.y + ad4.y; e1 = (e1 > 0.f) ? e1 : SLOPE * e1;
            float e2 = a.z + ad4.z; e2 = (e2 > 0.f) ? e2 : SLOPE * e2;
            float e3 = a.w + ad4.w; e3 = (e3 > 0.f) ? e3 : SLOPE * e3;
            sm[0] += __expf(e0); sm[1] += __expf(e1);
            sm[2] += __expf(e2); sm[3] += __expf(e3);
        }
    }
    #pragma unroll
    for (int hh = 0; hh < HH; hh++)
        #pragma unroll
        for (int off = 16; off > 0; off >>= 1)
            sm[hh] += __shfl_xor_sync(0xffffffffu, sm[hh], off);
    if (lane == 0)
        #pragma unroll
        for (int hh = 0; hh < HH; hh++) red[warp][hh] = sm[hh];
    __syncthreads();   // also publishes ssrc/sexp

    int head = (tid * VEC) / (CH / HH);
    float den = 1e-16f;
    #pragma unroll
    for (int w = 0; w < W; w++) den += red[w][head];
    float ih = 1.0f / den;

    float acc0 = 0.f, acc1 = 0.f;
    const int hoff = tid;   // __half2 offset within row (VEC=2)

    if (deg <= DCAP) {
        int j = 0;
        for (; j + 4 <= deg; j += 4) {
            int sA = ssrc[j], sB = ssrc[j + 1], sC = ssrc[j + 2], sD = ssrc[j + 3];
            float eA = sexp[(j    ) * HH + head];
            float eB = sexp[(j + 1) * HH + head];
            float eC = sexp[(j + 2) * HH + head];
            float eD = sexp[(j + 3) * HH + head];
            __half2 a0 = ((const __half2*)(h + (size_t)sA * CH))[hoff];
            __half2 b0 = ((const __half2*)(h + (size_t)sB * CH))[hoff];
            __half2 c0 = ((const __half2*)(h + (size_t)sC * CH))[hoff];
            __half2 d0 = ((const __half2*)(h + (size_t)sD * CH))[hoff];
            float2 f;
            f = __half22float2(a0); acc0 += eA * f.x; acc1 += eA * f.y;
            f = __half22float2(b0); acc0 += eB * f.x; acc1 += eB * f.y;
            f = __half22float2(c0); acc0 += eC * f.x; acc1 += eC * f.y;
            f = __half22float2(d0); acc0 += eD * f.x; acc1 += eD * f.y;
        }
        for (; j < deg; j++) {
            int s = ssrc[j];
            float e = sexp[j * HH + head];
            float2 f = __half22float2(((const __half2*)(h + (size_t)s * CH))[hoff]);
            acc0 += e * f.x; acc1 += e * f.y;
        }
    } else {
        for (int c0 = 0; c0 < deg; c0 += DCAP) {
            int cn = min(DCAP, deg - c0);
            __syncthreads();
            for (int j = tid; j < cn; j += THREADS) {
                int s = g_csr[s0 + c0 + j];
                ssrc[j] = s;
                float4 a = *(const float4*)&asrc[s * HH];
                float e0 = a.x + ad4.x; e0 = (e0 > 0.f) ? e0 : SLOPE * e0;
                float e1 = a.y + ad4.y; e1 = (e1 > 0.f) ? e1 : SLOPE * e1;
                float e2 = a.z + ad4.z; e2 = (e2 > 0.f) ? e2 : SLOPE * e2;
                float e3 = a.w + ad4.w; e3 = (e3 > 0.f) ? e3 : SLOPE * e3;
                sexp[j * HH + 0] = __expf(e0); sexp[j * HH + 1] = __expf(e1);
                sexp[j * HH + 2] = __expf(e2); sexp[j * HH + 3] = __expf(e3);
            }
            __syncthreads();
            for (int j = 0; j < cn; j++) {
                int s = ssrc[j];
                float e = sexp[j * HH + head];
                float2 f = __half22float2(((const __half2*)(h + (size_t)s * CH))[hoff]);
                acc0 += e * f.x; acc1 += e * f.y;
            }
        }
    }

    // elu + bias, write fp16
    float v0 = acc0 * ih + bias[tid * 2 + 0];
    float v1 = acc1 * ih + bias[tid * 2 + 1];
    v0 = (v0 > 0.f) ? v0 : expm1f(v0);
    v1 = (v1 > 0.f) ? v1 : expm1f(v1);
    ((__half2*)(out + (size_t)d * CH))[tid] = __floats2half2_rn(v0, v1);
}

// ---------------- launch ----------------------------------------------------
extern "C" void kernel_launch(void* const* d_in, const int* in_sizes, int n_in,
                              void* d_out, int out_size)
{
    const float* x   = (const float*)d_in[0];
    const int*   ei  = (const int*)  d_in[1];
    const float* W1  = (const float*)d_in[2];
    const float* as1 = (const float*)d_in[3];
    const float* ad1 = (const float*)d_in[4];
    const float* b1  = (const float*)d_in[5];
    const float* W2  = (const float*)d_in[6];
    const float* as2 = (const float*)d_in[7];
    const float* ad2 = (const float*)d_in[8];
    const float* b2  = (const float*)d_in[9];
    const float* Wf  = (const float*)d_in[10];
    const float* bf  = (const float*)d_in[11];
    float* out = (float*)d_out;

    __half *xh, *W1h, *W2h, *Wfh, *h1h, *h2h, *g1h, *g2h;
    float *pas, *pad;
    cudaGetSymbolAddress((void**)&xh,  g_xh);
    cudaGetSymbolAddress((void**)&W1h, g_W1h);
    cudaGetSymbolAddress((void**)&W2h, g_W2h);
    cudaGetSymbolAddress((void**)&Wfh, g_Wfh);
    cudaGetSymbolAddress((void**)&h1h, g_h1h);
    cudaGetSymbolAddress((void**)&h2h, g_h2h);
    cudaGetSymbolAddress((void**)&g1h, g_g1h);
    cudaGetSymbolAddress((void**)&g2h, g_g2h);
    cudaGetSymbolAddress((void**)&pas, g_asrc);
    cudaGetSymbolAddress((void**)&pad, g_adst);

    cudaFuncSetAttribute(gemm_f16_kernel<1, true>,
                         cudaFuncAttributeMaxDynamicSharedMemorySize, GEMM_SMEM);
    cudaFuncSetAttribute(gemm_f16_kernel<2, true>,
                         cudaFuncAttributeMaxDynamicSharedMemorySize, GEMM_SMEM);
    cudaFuncSetAttribute(gemm_f16_kernel<0, false>,
                         cudaFuncAttributeMaxDynamicSharedMemorySize, GEMM_SMEM);

    int grid_y = (NN + 255) / 256;   // 196

    // Launch order keeps GEMM1 as the 4th launch (ncu fixed-skip capture).
    zero_deg_kernel<<<(NN + 255) / 256, 256>>>();
    count_deg_kernel<<<(ETOT + 255) / 256, 256>>>(ei);
    convert_inputs_kernel<<<(NN * FIN / 4 + 255) / 256, 256>>>(x, W1, W2, Wf);

    // Layer 1 GEMM (+ fused attn coefs, fp16 h out)
    gemm_f16_kernel<1, true><<<dim3(CH1 / 128, grid_y), 256, GEMM_SMEM>>>(
        NN, CH1, FIN, xh, W1h, (float*)nullptr, h1h, CH1, CH1, (const float*)nullptr,
        as1, ad1, pas, pad);

    // CSR build
    scan1_kernel<<<NBLK, 256>>>();
    scan2_kernel<<<1, 256>>>();
    scan3_kernel<<<NBLK, 256>>>();
    scatter_edges_kernel<<<(ETOT + 255) / 256, 256>>>(ei);

    gat_agg_kernel<CH1, 256><<<NN, 256>>>(h1h, pas, pad, b1, g1h);

    // Layer 2
    gemm_f16_kernel<2, true><<<dim3(CH2 / 128, grid_y), 256, GEMM_SMEM>>>(
        NN, CH2, CH1, g1h, W2h, (float*)nullptr, h2h, CH2, CH2, (const float*)nullptr,
        as2, ad2, pas, pad);
    gat_agg_kernel<CH2, 128><<<NN, 128>>>(h2h, pas, pad, b2, g2h);

    // Final classifier: out[N,50] = g2 @ Wfpad + bf
    gemm_f16_kernel<0, false><<<dim3(1, grid_y), 256, GEMM_SMEM>>>(
        NN, 128, CH2, g2h, Wfh, out, (__half*)nullptr, NCLS, NCLS, bf,
        (const float*)nullptr, (const float*)nullptr,
        (float*)nullptr, (float*)nullptr);
}

// round 12
// speedup vs baseline: 1.4873x; 1.1193x over previous
#include <cuda_runtime.h>
#include <cuda_fp16.h>
#include <math.h>
#include <stdint.h>

// Problem constants (fixed by the dataset)
#define NN    50000
#define EE    800000
#define ETOT  850000        // EE + NN self loops
#define FIN   256
#define HH    4
#define CC1   128
#define CC2   64
#define CH1   512           // HH*CC1
#define CH2   256           // HH*CC2
#define NCLS  50
#define SLOPE 0.2f
#define NBLK  ((NN + 255) / 256)

// ---------------- scratch (device globals; no allocations allowed) ----------
__device__ __half g_xh [NN * FIN];    // x   in fp16 (GEMM1 A)
__device__ __half g_W1h[FIN * CH1];   // W1  fp16
__device__ __half g_W2h[CH1 * CH2];   // W2  fp16
__device__ __half g_Wfh[CH2 * 128];   // Wf  fp16, zero-padded to 128 cols
__device__ __half g_h1h[NN * CH1];    // x @ W1  (messages, fp16)
__device__ __half g_h2h[NN * CH2];    // g1 @ W2 (messages, fp16)
__device__ __half g_g1h[NN * CH1];    // elu(agg1 + b1), fp16 (GEMM2 A)
__device__ __half g_g2h[NN * CH2];    // elu(agg2 + b2), fp16 (GEMM3 A)
__device__ float g_asrc[NN * HH];
__device__ float g_adst[NN * HH];
__device__ int   g_deg[NN];
__device__ int   g_rowptr[NN + 1];
__device__ int   g_cursor[NN];
__device__ int   g_csr[ETOT];
__device__ int   g_blocksum[256];
__device__ int   g_blockoff[256];

// ---------------- CSR construction ------------------------------------------
__global__ void zero_deg_kernel() {
    int i = blockIdx.x * blockDim.x + threadIdx.x;
    if (i < NN) g_deg[i] = 0;
}

__global__ void count_deg_kernel(const int* __restrict__ ei) {
    int e = blockIdx.x * blockDim.x + threadIdx.x;
    if (e >= ETOT) return;
    int d = (e < EE) ? ei[EE + e] : (e - EE);   // self loop for e >= EE
    atomicAdd(&g_deg[d], 1);
}

__global__ __launch_bounds__(256) void scan1_kernel() {
    int b = blockIdx.x;
    int i = b * 256 + threadIdx.x;
    int v = (i < NN) ? g_deg[i] : 0;
    int lane = threadIdx.x & 31, w = threadIdx.x >> 5;
    int s = v;
    #pragma unroll
    for (int off = 1; off < 32; off <<= 1) {
        int t = __shfl_up_sync(0xffffffffu, s, off);
        if (lane >= off) s += t;
    }
    __shared__ int ws[8];
    if (lane == 31) ws[w] = s;
    __syncthreads();
    if (threadIdx.x == 0) {
        int acc = 0;
        #pragma unroll
        for (int j = 0; j < 8; j++) { int t = ws[j]; ws[j] = acc; acc += t; }
        g_blocksum[b] = acc;
    }
    __syncthreads();
    s += ws[w];
    if (i < NN) g_rowptr[i + 1] = s;
}

__global__ __launch_bounds__(256) void scan2_kernel() {
    int t = threadIdx.x;
    int v = (t < NBLK) ? g_blocksum[t] : 0;
    int lane = t & 31, w = t >> 5;
    int s = v;
    #pragma unroll
    for (int off = 1; off < 32; off <<= 1) {
        int u = __shfl_up_sync(0xffffffffu, s, off);
        if (lane >= off) s += u;
    }
    __shared__ int ws[8];
    if (lane == 31) ws[w] = s;
    __syncthreads();
    if (t == 0) {
        int acc = 0;
        #pragma unroll
        for (int j = 0; j < 8; j++) { int u = ws[j]; ws[j] = acc; acc += u; }
    }
    __syncthreads();
    s += ws[w];
    g_blockoff[t] = s - v;
}

__global__ void scan3_kernel() {
    int i = blockIdx.x * blockDim.x + threadIdx.x;
    if (i >= NN) return;
    int off  = g_blockoff[i >> 8];
    int incl = g_rowptr[i + 1] + off;
    g_rowptr[i + 1] = incl;
    g_cursor[i]     = incl - g_deg[i];
    if (i == 0) g_rowptr[0] = 0;
}

__global__ void scatter_edges_kernel(const int* __restrict__ ei) {
    int e = blockIdx.x * blockDim.x + threadIdx.x;
    if (e >= ETOT) return;
    int s, d;
    if (e < EE) { s = ei[e]; d = ei[EE + e]; }
    else        { s = d = e - EE; }
    int pos = atomicAdd(&g_cursor[d], 1);
    g_csr[pos] = s;
}

// ---------------- fp32 -> fp16 input conversion (one kernel) ----------------
__global__ __launch_bounds__(256) void convert_inputs_kernel(
    const float* __restrict__ x, const float* __restrict__ W1,
    const float* __restrict__ W2, const float* __restrict__ Wf)
{
    int i = blockIdx.x * blockDim.x + threadIdx.x;   // float4 index for x
    if (i < NN * FIN / 4) {
        float4 v = *(const float4*)(x + i * 4);
        __half2* p = (__half2*)(g_xh + i * 4);
        p[0] = __floats2half2_rn(v.x, v.y);
        p[1] = __floats2half2_rn(v.z, v.w);
    }
    if (i < FIN * CH1 / 4) {
        float4 v = *(const float4*)(W1 + i * 4);
        __half2* p = (__half2*)(g_W1h + i * 4);
        p[0] = __floats2half2_rn(v.x, v.y);
        p[1] = __floats2half2_rn(v.z, v.w);
    }
    if (i < CH1 * CH2 / 4) {
        float4 v = *(const float4*)(W2 + i * 4);
        __half2* p = (__half2*)(g_W2h + i * 4);
        p[0] = __floats2half2_rn(v.x, v.y);
        p[1] = __floats2half2_rn(v.z, v.w);
    }
    if (i < CH2 * 128) {
        int r = i >> 7, cc = i & 127;
        g_Wfh[i] = __float2half((cc < NCLS) ? Wf[r * NCLS + cc] : 0.f);
    }
}

// ---------------- fp16 tensor-core GEMM: 256x128 tile, 3-stage cp.async -----
// C[M,ncols] = A[M,K] @ B[K,N] (+bias). A,B fp16 in gmem. N mult of 128,
// K mult of 32. 8 warps as 4x2 -> warp tile 64x64 (m16n8k16).
// 3 buffers -> issue(kt+2) writes the buffer whose readers finished before the
// PREVIOUS iteration's barrier, so only ONE __syncthreads per K-iteration.
#define SAH 40     // A smem row stride (halfs): 80 B, ldmatrix conflict-free
#define SBH 136    // B smem row stride (halfs): 272 B, conflict-free
#define A_BUF (256 * SAH)
#define B_BUF (32 * SBH)
#define STAGES 3
#define GEMM_SMEM ((STAGES * (A_BUF + B_BUF)) * 2)   // 87552 bytes

__device__ __forceinline__ void ldm_x4(uint32_t* r, uint32_t addr) {
    asm volatile("ldmatrix.sync.aligned.m8n8.x4.shared.b16 {%0,%1,%2,%3}, [%4];"
                 : "=r"(r[0]), "=r"(r[1]), "=r"(r[2]), "=r"(r[3]) : "r"(addr));
}
__device__ __forceinline__ void ldm_x4_t(uint32_t* r, uint32_t addr) {
    asm volatile("ldmatrix.sync.aligned.m8n8.x4.trans.shared.b16 {%0,%1,%2,%3}, [%4];"
                 : "=r"(r[0]), "=r"(r[1]), "=r"(r[2]), "=r"(r[3]) : "r"(addr));
}
__device__ __forceinline__ void mma_f16(float* c, uint32_t a0, uint32_t a1,
                                        uint32_t a2, uint32_t a3,
                                        uint32_t b0, uint32_t b1) {
    asm volatile(
        "mma.sync.aligned.m16n8k16.row.col.f32.f16.f16.f32 "
        "{%0,%1,%2,%3},{%4,%5,%6,%7},{%8,%9},{%0,%1,%2,%3};\n"
        : "+f"(c[0]), "+f"(c[1]), "+f"(c[2]), "+f"(c[3])
        : "r"(a0), "r"(a1), "r"(a2), "r"(a3), "r"(b0), "r"(b1));
}
__device__ __forceinline__ void cp16(uint32_t dst, const void* src, bool ok) {
    int sz = ok ? 16 : 0;
    asm volatile("cp.async.ca.shared.global [%0], [%1], 16, %2;"
                 :: "r"(dst), "l"(src), "r"(sz));
}

template <int HPB, bool HALFOUT>
__global__ __launch_bounds__(256) void gemm_f16_kernel(
    int M, int N, int K,
    const __half* __restrict__ A, const __half* __restrict__ B,
    float* __restrict__ Cf, __half* __restrict__ Chalf,
    int ldc, int ncols, const float* __restrict__ bias,
    const float* __restrict__ avs, const float* __restrict__ avd,
    float* __restrict__ o_src, float* __restrict__ o_dst)
{
    extern __shared__ __half smem[];
    uint32_t smem_u32 = (uint32_t)__cvta_generic_to_shared(smem);

    int tid  = threadIdx.x;
    int row0 = blockIdx.y * 256;
    int col0 = blockIdx.x * 128;
    int warp = tid >> 5, lane = tid & 31;
    int wm = warp >> 1, wn = warp & 1;       // 4x2 warps -> warp tile 64x64
    int tg = lane >> 2, tig = lane & 3;

    bool aok = (row0 + tid) < M;

    auto issue = [&](int kt, int buf) {
        const __half* asrc = A + (size_t)(row0 + tid) * K + kt * 32;
        uint32_t adst = smem_u32 + (uint32_t)((buf * A_BUF + tid * SAH) * 2);
        #pragma unroll
        for (int i = 0; i < 4; i++)
            cp16(adst + i * 16, asrc + i * 8, aok);
        int brow = tid >> 3, bch = (tid & 7) * 2;
        const __half* bsrc = B + (size_t)(kt * 32 + brow) * N + col0 + bch * 8;
        uint32_t bdst = smem_u32 +
            (uint32_t)((STAGES * A_BUF + buf * B_BUF + brow * SBH + bch * 8) * 2);
        cp16(bdst,      bsrc,     true);
        cp16(bdst + 16, bsrc + 8, true);
        asm volatile("cp.async.commit_group;");
    };

    float c[4][8][4];
    #pragma unroll
    for (int mi = 0; mi < 4; mi++)
        #pragma unroll
        for (int ni = 0; ni < 8; ni++)
            #pragma unroll
            for (int j = 0; j < 4; j++) c[mi][ni][j] = 0.0f;

    int la = lane & 15, lh = lane >> 4;
    uint32_t a_lane = (uint32_t)((la * SAH + lh * 8) * 2);
    uint32_t b_lane = (uint32_t)((la * SBH + lh * 8) * 2);

    auto compute = [&](int buf) {
        uint32_t sa = smem_u32 + (uint32_t)(buf * A_BUF * 2) + a_lane
                    + (uint32_t)(wm * 64 * SAH * 2);
        uint32_t sb = smem_u32 + (uint32_t)((STAGES * A_BUF + buf * B_BUF) * 2) + b_lane
                    + (uint32_t)(wn * 64 * 2);
        #pragma unroll
        for (int ks = 0; ks < 2; ks++) {
            int kk = ks * 16;
            uint32_t af[4][4], bf[4][4];
            #pragma unroll
            for (int mi = 0; mi < 4; mi++)
                ldm_x4(af[mi], sa + (uint32_t)((mi * 16 * SAH + kk) * 2));
            #pragma unroll
            for (int np = 0; np < 4; np++)
                ldm_x4_t(bf[np], sb + (uint32_t)((kk * SBH + np * 16) * 2));
            #pragma unroll
            for (int mi = 0; mi < 4; mi++)
                #pragma unroll
                for (int np = 0; np < 4; np++) {
                    mma_f16(c[mi][np * 2],     af[mi][0], af[mi][1], af[mi][2], af[mi][3],
                            bf[np][0], bf[np][1]);
                    mma_f16(c[mi][np * 2 + 1], af[mi][0], af[mi][1], af[mi][2], af[mi][3],
                            bf[np][2], bf[np][3]);
                }
        }
    };

    int KT = K / 32;    // 8, 16, or 8 for our three shapes
    // prologue: 2 stages in flight, stage 0 ready
    issue(0, 0);
    issue(1, 1);
    asm volatile("cp.async.wait_group 1;");
    __syncthreads();

    int cbuf = 0, wbuf = 2;   // compute buffer, next write buffer
    for (int kt = 0; kt < KT; kt++) {
        compute(cbuf);
        if (kt + 2 < KT) {
            issue(kt + 2, wbuf);
            asm volatile("cp.async.wait_group 1;");   // stage kt+1 complete
        } else {
            asm volatile("cp.async.wait_group 0;");
        }
        __syncthreads();
        cbuf = (cbuf == 2) ? 0 : cbuf + 1;
        wbuf = (wbuf == 2) ? 0 : wbuf + 1;
    }

    // ---- fused attention-coefficient epilogue (overlay dead smem) ----
    if (HPB > 0) {
        float* sm_src = (float*)smem;          // [2][256]
        float* sm_dst = sm_src + 512;          // [2][256]
        float sa_[4][2], da_[4][2];
        #pragma unroll
        for (int mi = 0; mi < 4; mi++) {
            sa_[mi][0] = sa_[mi][1] = 0.f;
            da_[mi][0] = da_[mi][1] = 0.f;
        }
        #pragma unroll
        for (int ni = 0; ni < 8; ni++) {
            int cl = wn * 64 + ni * 8 + tig * 2;
            float ws0 = avs[col0 + cl], ws1 = avs[col0 + cl + 1];
            float wd0 = avd[col0 + cl], wd1 = avd[col0 + cl + 1];
            #pragma unroll
            for (int mi = 0; mi < 4; mi++) {
                sa_[mi][0] += c[mi][ni][0] * ws0 + c[mi][ni][1] * ws1;
                da_[mi][0] += c[mi][ni][0] * wd0 + c[mi][ni][1] * wd1;
                sa_[mi][1] += c[mi][ni][2] * ws0 + c[mi][ni][3] * ws1;
                da_[mi][1] += c[mi][ni][2] * wd0 + c[mi][ni][3] * wd1;
            }
        }
        #pragma unroll
        for (int mi = 0; mi < 4; mi++)
            #pragma unroll
            for (int p = 0; p < 2; p++) {
                sa_[mi][p] += __shfl_xor_sync(0xffffffffu, sa_[mi][p], 1);
                sa_[mi][p] += __shfl_xor_sync(0xffffffffu, sa_[mi][p], 2);
                da_[mi][p] += __shfl_xor_sync(0xffffffffu, da_[mi][p], 1);
                da_[mi][p] += __shfl_xor_sync(0xffffffffu, da_[mi][p], 2);
            }
        if (tig == 0) {
            #pragma unroll
            for (int mi = 0; mi < 4; mi++) {
                int rl = wm * 64 + mi * 16 + tg;
                sm_src[wn * 256 + rl]     = sa_[mi][0];
                sm_src[wn * 256 + rl + 8] = sa_[mi][1];
                sm_dst[wn * 256 + rl]     = da_[mi][0];
                sm_dst[wn * 256 + rl + 8] = da_[mi][1];
            }
        }
        __syncthreads();
        {
            int r = row0 + tid;
            if (r < M) {
                if (HPB == 1) {
                    o_src[r * HH + blockIdx.x] = sm_src[tid] + sm_src[256 + tid];
                    o_dst[r * HH + blockIdx.x] = sm_dst[tid] + sm_dst[256 + tid];
                } else {
                    int hb = blockIdx.x * 2;
                    o_src[r * HH + hb]     = sm_src[tid];
                    o_src[r * HH + hb + 1] = sm_src[256 + tid];
                    o_dst[r * HH + hb]     = sm_dst[tid];
                    o_dst[r * HH + hb + 1] = sm_dst[256 + tid];
                }
            }
        }
    }

    // ---- C write ----
    #pragma unroll
    for (int mi = 0; mi < 4; mi++) {
        int r = row0 + wm * 64 + mi * 16 + tg;
        #pragma unroll
        for (int ni = 0; ni < 8; ni++) {
            int cc = col0 + wn * 64 + ni * 8 + tig * 2;
            if (cc >= ncols) continue;
            if (HALFOUT) {
                if (r < M)
                    *(__half2*)(Chalf + (size_t)r * ldc + cc) =
                        __floats2half2_rn(c[mi][ni][0], c[mi][ni][1]);
                if (r + 8 < M)
                    *(__half2*)(Chalf + (size_t)(r + 8) * ldc + cc) =
                        __floats2half2_rn(c[mi][ni][2], c[mi][ni][3]);
            } else {
                float b0 = bias ? bias[cc]     : 0.f;
                float b1 = bias ? bias[cc + 1] : 0.f;
                if (r < M) {
                    Cf[(size_t)r * ldc + cc]     = c[mi][ni][0] + b0;
                    Cf[(size_t)r * ldc + cc + 1] = c[mi][ni][1] + b1;
                }
                if (r + 8 < M) {
                    Cf[(size_t)(r + 8) * ldc + cc]     = c[mi][ni][2] + b0;
                    Cf[(size_t)(r + 8) * ldc + cc + 1] = c[mi][ni][3] + b1;
                }
            }
        }
    }
}

// ---------------- GAT softmax + aggregation (one block per dst node) --------
// EXACT R8 configuration: 128 threads, VEC=CH/128 (proven; 256-thread variant
// regressed because pass-2's serial loop length is thread-count-invariant).
#define DCAP 512
template <int CH>
__global__ __launch_bounds__(128) void gat_agg_kernel(
    const __half* __restrict__ h,
    const float* __restrict__ asrc, const float* __restrict__ adst,
    const float* __restrict__ bias, __half* __restrict__ out)
{
    constexpr int VEC = CH / 128;             // 4 (layer1) or 2 (layer2)
    __shared__ int   ssrc[DCAP];
    __shared__ float sexp[DCAP * HH];
    __shared__ float red[4][HH];

    int d    = blockIdx.x;
    int tid  = threadIdx.x;
    int lane = tid & 31, warp = tid >> 5;
    int s0   = g_rowptr[d];
    int deg  = g_rowptr[d + 1] - s0;

    float4 ad4 = *(const float4*)&adst[d * HH];

    float sm[HH] = {0.f, 0.f, 0.f, 0.f};
    if (deg <= DCAP) {
        for (int j = tid; j < deg; j += 128) {
            int s = g_csr[s0 + j];
            ssrc[j] = s;
            float4 a = *(const float4*)&asrc[s * HH];
            float e0 = a.x + ad4.x; e0 = (e0 > 0.f) ? e0 : SLOPE * e0; e0 = __expf(e0);
            float e1 = a.y + ad4.y; e1 = (e1 > 0.f) ? e1 : SLOPE * e1; e1 = __expf(e1);
            float e2 = a.z + ad4.z; e2 = (e2 > 0.f) ? e2 : SLOPE * e2; e2 = __expf(e2);
            float e3 = a.w + ad4.w; e3 = (e3 > 0.f) ? e3 : SLOPE * e3; e3 = __expf(e3);
            sexp[j * HH + 0] = e0; sexp[j * HH + 1] = e1;
            sexp[j * HH + 2] = e2; sexp[j * HH + 3] = e3;
            sm[0] += e0; sm[1] += e1; sm[2] += e2; sm[3] += e3;
        }
    } else {
        for (int j = tid; j < deg; j += 128) {
            int s = g_csr[s0 + j];
            float4 a = *(const float4*)&asrc[s * HH];
            float e0 = a.x + ad4.x; e0 = (e0 > 0.f) ? e0 : SLOPE * e0;
            float e1 = a.y + ad4.y; e1 = (e1 > 0.f) ? e1 : SLOPE * e1;
            float e2 = a.z + ad4.z; e2 = (e2 > 0.f) ? e2 : SLOPE * e2;
            float e3 = a.w + ad4.w; e3 = (e3 > 0.f) ? e3 : SLOPE * e3;
            sm[0] += __expf(e0); sm[1] += __expf(e1);
            sm[2] += __expf(e2); sm[3] += __expf(e3);
        }
    }
    #pragma unroll
    for (int hh = 0; hh < HH; hh++)
        #pragma unroll
        for (int off = 16; off > 0; off >>= 1)
            sm[hh] += __shfl_xor_sync(0xffffffffu, sm[hh], off);
    if (lane == 0)
        #pragma unroll
        for (int hh = 0; hh < HH; hh++) red[warp][hh] = sm[hh];
    __syncthreads();   // also publishes ssrc/sexp

    int head = tid >> 5;
    float ih = 1.0f / (red[0][head] + red[1][head] + red[2][head] + red[3][head] + 1e-16f);

    float acc[VEC];
    #pragma unroll
    for (int j = 0; j < VEC; j++) acc[j] = 0.f;

    const int hoff = tid * (VEC / 2);   // __half2 offset within row

    if (deg <= DCAP) {
        int j = 0;
        for (; j + 4 <= deg; j += 4) {
            int sA = ssrc[j], sB = ssrc[j + 1], sC = ssrc[j + 2], sD = ssrc[j + 3];
            float eA = sexp[(j    ) * HH + head];
            float eB = sexp[(j + 1) * HH + head];
            float eC = sexp[(j + 2) * HH + head];
            float eD = sexp[(j + 3) * HH + head];
            const __half2* pA = (const __half2*)(h + (size_t)sA * CH) + hoff;
            const __half2* pB = (const __half2*)(h + (size_t)sB * CH) + hoff;
            const __half2* pC = (const __half2*)(h + (size_t)sC * CH) + hoff;
            const __half2* pD = (const __half2*)(h + (size_t)sD * CH) + hoff;
            if (VEC == 4) {
                __half2 a0 = pA[0], a1 = pA[1];
                __half2 b0 = pB[0], b1 = pB[1];
                __half2 c0 = pC[0], c1 = pC[1];
                __half2 d0 = pD[0], d1 = pD[1];
                float2 f;
                f = __half22float2(a0); acc[0] += eA * f.x; acc[1] += eA * f.y;
                f = __half22float2(a1); acc[2] += eA * f.x; acc[3] += eA * f.y;
                f = __half22float2(b0); acc[0] += eB * f.x; acc[1] += eB * f.y;
                f = __half22float2(b1); acc[2] += eB * f.x; acc[3] += eB * f.y;
                f = __half22float2(c0); acc[0] += eC * f.x; acc[1] += eC * f.y;
                f = __half22float2(c1); acc[2] += eC * f.x; acc[3] += eC * f.y;
                f = __half22float2(d0); acc[0] += eD * f.x; acc[1] += eD * f.y;
                f = __half22float2(d1); acc[2] += eD * f.x; acc[3] += eD * f.y;
            } else {
                __half2 a0 = pA[0], b0 = pB[0], c0 = pC[0], d0 = pD[0];
                float2 f;
                f = __half22float2(a0); acc[0] += eA * f.x; acc[1] += eA * f.y;
                f = __half22float2(b0); acc[0] += eB * f.x; acc[1] += eB * f.y;
                f = __half22float2(c0); acc[0] += eC * f.x; acc[1] += eC * f.y;
                f = __half22float2(d0); acc[0] += eD * f.x; acc[1] += eD * f.y;
            }
        }
        for (; j < deg; j++) {
            int s = ssrc[j];
            float e = sexp[j * HH + head];
            const __half2* p = (const __half2*)(h + (size_t)s * CH) + hoff;
            #pragma unroll
            for (int q = 0; q < VEC / 2; q++) {
                float2 f = __half22float2(p[q]);
                acc[q * 2]     += e * f.x;
                acc[q * 2 + 1] += e * f.y;
            }
        }
    } else {
        for (int c0 = 0; c0 < deg; c0 += DCAP) {
            int cn = min(DCAP, deg - c0);
            __syncthreads();
            for (int j = tid; j < cn; j += 128) {
                int s = g_csr[s0 + c0 + j];
                ssrc[j] = s;
                float4 a = *(const float4*)&asrc[s * HH];
                float e0 = a.x + ad4.x; e0 = (e0 > 0.f) ? e0 : SLOPE * e0;
                float e1 = a.y + ad4.y; e1 = (e1 > 0.f) ? e1 : SLOPE * e1;
                float e2 = a.z + ad4.z; e2 = (e2 > 0.f) ? e2 : SLOPE * e2;
                float e3 = a.w + ad4.w; e3 = (e3 > 0.f) ? e3 : SLOPE * e3;
                sexp[j * HH + 0] = __expf(e0); sexp[j * HH + 1] = __expf(e1);
                sexp[j * HH + 2] = __expf(e2); sexp[j * HH + 3] = __expf(e3);
            }
            __syncthreads();
            for (int j = 0; j < cn; j++) {
                int s = ssrc[j];
                float e = sexp[j * HH + head];
                const __half2* p = (const __half2*)(h + (size_t)s * CH) + hoff;
                #pragma unroll
                for (int q = 0; q < VEC / 2; q++) {
                    float2 f = __half22float2(p[q]);
                    acc[q * 2]     += e * f.x;
                    acc[q * 2 + 1] += e * f.y;
                }
            }
        }
    }

    // elu + bias, write fp16
    float v0 = acc[0] * ih + bias[tid * VEC + 0];
    float v1 = acc[1] * ih + bias[tid * VEC + 1];
    v0 = (v0 > 0.f) ? v0 : expm1f(v0);
    v1 = (v1 > 0.f) ? v1 : expm1f(v1);
    __half2* op = (__half2*)(out + (size_t)d * CH + tid * VEC);
    op[0] = __floats2half2_rn(v0, v1);
    if (VEC == 4) {
        float v2 = acc[2] * ih + bias[tid * VEC + 2];
        float v3 = acc[3] * ih + bias[tid * VEC + 3];
        v2 = (v2 > 0.f) ? v2 : expm1f(v2);
        v3 = (v3 > 0.f) ? v3 : expm1f(v3);
        op[1] = __floats2half2_rn(v2, v3);
    }
}

// ---------------- launch ----------------------------------------------------
extern "C" void kernel_launch(void* const* d_in, const int* in_sizes, int n_in,
                              void* d_out, int out_size)
{
    const float* x   = (const float*)d_in[0];
    const int*   ei  = (const int*)  d_in[1];
    const float* W1  = (const float*)d_in[2];
    const float* as1 = (const float*)d_in[3];
    const float* ad1 = (const float*)d_in[4];
    const float* b1  = (const float*)d_in[5];
    const float* W2  = (const float*)d_in[6];
    const float* as2 = (const float*)d_in[7];
    const float* ad2 = (const float*)d_in[8];
    const float* b2  = (const float*)d_in[9];
    const float* Wf  = (const float*)d_in[10];
    const float* bf  = (const float*)d_in[11];
    float* out = (float*)d_out;

    __half *xh, *W1h, *W2h, *Wfh, *h1h, *h2h, *g1h, *g2h;
    float *pas, *pad;
    cudaGetSymbolAddress((void**)&xh,  g_xh);
    cudaGetSymbolAddress((void**)&W1h, g_W1h);
    cudaGetSymbolAddress((void**)&W2h, g_W2h);
    cudaGetSymbolAddress((void**)&Wfh, g_Wfh);
    cudaGetSymbolAddress((void**)&h1h, g_h1h);
    cudaGetSymbolAddress((void**)&h2h, g_h2h);
    cudaGetSymbolAddress((void**)&g1h, g_g1h);
    cudaGetSymbolAddress((void**)&g2h, g_g2h);
    cudaGetSymbolAddress((void**)&pas, g_asrc);
    cudaGetSymbolAddress((void**)&pad, g_adst);

    cudaFuncSetAttribute(gemm_f16_kernel<1, true>,
                         cudaFuncAttributeMaxDynamicSharedMemorySize, GEMM_SMEM);
    cudaFuncSetAttribute(gemm_f16_kernel<2, true>,
                         cudaFuncAttributeMaxDynamicSharedMemorySize, GEMM_SMEM);
    cudaFuncSetAttribute(gemm_f16_kernel<0, false>,
                         cudaFuncAttributeMaxDynamicSharedMemorySize, GEMM_SMEM);

    int grid_y = (NN + 255) / 256;   // 196

    // Launch order keeps GEMM1 as the 4th launch (ncu fixed-skip capture).
    zero_deg_kernel<<<(NN + 255) / 256, 256>>>();
    count_deg_kernel<<<(ETOT + 255) / 256, 256>>>(ei);
    convert_inputs_kernel<<<(NN * FIN / 4 + 255) / 256, 256>>>(x, W1, W2, Wf);

    // Layer 1 GEMM (+ fused attn coefs, fp16 h out)
    gemm_f16_kernel<1, true><<<dim3(CH1 / 128, grid_y), 256, GEMM_SMEM>>>(
        NN, CH1, FIN, xh, W1h, (float*)nullptr, h1h, CH1, CH1, (const float*)nullptr,
        as1, ad1, pas, pad);

    // CSR build
    scan1_kernel<<<NBLK, 256>>>();
    scan2_kernel<<<1, 256>>>();
    scan3_kernel<<<NBLK, 256>>>();
    scatter_edges_kernel<<<(ETOT + 255) / 256, 256>>>(ei);

    gat_agg_kernel<CH1><<<NN, 128>>>(h1h, pas, pad, b1, g1h);

    // Layer 2
    gemm_f16_kernel<2, true><<<dim3(CH2 / 128, grid_y), 256, GEMM_SMEM>>>(
        NN, CH2, CH1, g1h, W2h, (float*)nullptr, h2h, CH2, CH2, (const float*)nullptr,
        as2, ad2, pas, pad);
    gat_agg_kernel<CH2><<<NN, 128>>>(h2h, pas, pad, b2, g2h);

    // Final classifier: out[N,50] = g2 @ Wfpad + bf
    gemm_f16_kernel<0, false><<<dim3(1, grid_y), 256, GEMM_SMEM>>>(
        NN, 128, CH2, g2h, Wfh, out, (__half*)nullptr, NCLS, NCLS, bf,
        (const float*)nullptr, (const float*)nullptr,
        (float*)nullptr, (float*)nullptr);
}

// round 14
// speedup vs baseline: 1.5369x; 1.0333x over previous
#include <cuda_runtime.h>
#include <cuda_fp16.h>
#include <math.h>
#include <stdint.h>

// Problem constants (fixed by the dataset)
#define NN    50000
#define EE    800000
#define ETOT  850000        // EE + NN self loops
#define FIN   256
#define HH    4
#define CC1   128
#define CC2   64
#define CH1   512           // HH*CC1
#define CH2   256           // HH*CC2
#define NCLS  50
#define SLOPE 0.2f
#define NBLK  ((NN + 255) / 256)

// ---------------- scratch (device globals; no allocations allowed) ----------
__device__ __half g_xh [NN * FIN];    // x   in fp16 (GEMM1 A)
__device__ __half g_W1h[FIN * CH1];   // W1  fp16
__device__ __half g_W2h[CH1 * CH2];   // W2  fp16
__device__ __half g_Wfh[CH2 * 128];   // Wf  fp16, zero-padded to 128 cols
__device__ __half g_h1h[NN * CH1];    // x @ W1  (messages, fp16)
__device__ __half g_h2h[NN * CH2];    // g1 @ W2 (messages, fp16)
__device__ __half g_g1h[NN * CH1];    // elu(agg1 + b1), fp16 (GEMM2 A)
__device__ __half g_g2h[NN * CH2];    // elu(agg2 + b2), fp16 (GEMM3 A)
__device__ float g_asrc[NN * HH];
__device__ float g_adst[NN * HH];
__device__ int   g_deg[NN];
__device__ int   g_rowptr[NN + 1];
__device__ int   g_cursor[NN];
__device__ int   g_csr[ETOT];
__device__ int   g_blocksum[256];
__device__ int   g_blockoff[256];

// ---------------- CSR construction ------------------------------------------
__global__ void zero_deg_kernel() {
    int i = blockIdx.x * blockDim.x + threadIdx.x;
    if (i < NN) g_deg[i] = 0;
}

__global__ void count_deg_kernel(const int* __restrict__ ei) {
    int e = blockIdx.x * blockDim.x + threadIdx.x;
    if (e >= ETOT) return;
    int d = (e < EE) ? ei[EE + e] : (e - EE);   // self loop for e >= EE
    atomicAdd(&g_deg[d], 1);
}

__global__ __launch_bounds__(256) void scan1_kernel() {
    int b = blockIdx.x;
    int i = b * 256 + threadIdx.x;
    int v = (i < NN) ? g_deg[i] : 0;
    int lane = threadIdx.x & 31, w = threadIdx.x >> 5;
    int s = v;
    #pragma unroll
    for (int off = 1; off < 32; off <<= 1) {
        int t = __shfl_up_sync(0xffffffffu, s, off);
        if (lane >= off) s += t;
    }
    __shared__ int ws[8];
    if (lane == 31) ws[w] = s;
    __syncthreads();
    if (threadIdx.x == 0) {
        int acc = 0;
        #pragma unroll
        for (int j = 0; j < 8; j++) { int t = ws[j]; ws[j] = acc; acc += t; }
        g_blocksum[b] = acc;
    }
    __syncthreads();
    s += ws[w];
    if (i < NN) g_rowptr[i + 1] = s;
}

__global__ __launch_bounds__(256) void scan2_kernel() {
    int t = threadIdx.x;
    int v = (t < NBLK) ? g_blocksum[t] : 0;
    int lane = t & 31, w = t >> 5;
    int s = v;
    #pragma unroll
    for (int off = 1; off < 32; off <<= 1) {
        int u = __shfl_up_sync(0xffffffffu, s, off);
        if (lane >= off) s += u;
    }
    __shared__ int ws[8];
    if (lane == 31) ws[w] = s;
    __syncthreads();
    if (t == 0) {
        int acc = 0;
        #pragma unroll
        for (int j = 0; j < 8; j++) { int u = ws[j]; ws[j] = acc; acc += u; }
    }
    __syncthreads();
    s += ws[w];
    g_blockoff[t] = s - v;
}

__global__ void scan3_kernel() {
    int i = blockIdx.x * blockDim.x + threadIdx.x;
    if (i >= NN) return;
    int off  = g_blockoff[i >> 8];
    int incl = g_rowptr[i + 1] + off;
    g_rowptr[i + 1] = incl;
    g_cursor[i]     = incl - g_deg[i];
    if (i == 0) g_rowptr[0] = 0;
}

__global__ void scatter_edges_kernel(const int* __restrict__ ei) {
    int e = blockIdx.x * blockDim.x + threadIdx.x;
    if (e >= ETOT) return;
    int s, d;
    if (e < EE) { s = ei[e]; d = ei[EE + e]; }
    else        { s = d = e - EE; }
    int pos = atomicAdd(&g_cursor[d], 1);
    g_csr[pos] = s;
}

// ---------------- fp32 -> fp16 input conversion (one kernel) ----------------
__global__ __launch_bounds__(256) void convert_inputs_kernel(
    const float* __restrict__ x, const float* __restrict__ W1,
    const float* __restrict__ W2, const float* __restrict__ Wf)
{
    int i = blockIdx.x * blockDim.x + threadIdx.x;   // float4 index for x
    if (i < NN * FIN / 4) {
        float4 v = *(const float4*)(x + i * 4);
        __half2* p = (__half2*)(g_xh + i * 4);
        p[0] = __floats2half2_rn(v.x, v.y);
        p[1] = __floats2half2_rn(v.z, v.w);
    }
    if (i < FIN * CH1 / 4) {
        float4 v = *(const float4*)(W1 + i * 4);
        __half2* p = (__half2*)(g_W1h + i * 4);
        p[0] = __floats2half2_rn(v.x, v.y);
        p[1] = __floats2half2_rn(v.z, v.w);
    }
    if (i < CH1 * CH2 / 4) {
        float4 v = *(const float4*)(W2 + i * 4);
        __half2* p = (__half2*)(g_W2h + i * 4);
        p[0] = __floats2half2_rn(v.x, v.y);
        p[1] = __floats2half2_rn(v.z, v.w);
    }
    if (i < CH2 * 128) {
        int r = i >> 7, cc = i & 127;
        g_Wfh[i] = __float2half((cc < NCLS) ? Wf[r * NCLS + cc] : 0.f);
    }
}

// ---------------- fp16 tensor-core GEMM: 256x128 tile, 3-stage cp.async -----
// (R12 configuration: proven best.)
#define SAH 40     // A smem row stride (halfs): 80 B, ldmatrix conflict-free
#define SBH 136    // B smem row stride (halfs): 272 B, conflict-free
#define A_BUF (256 * SAH)
#define B_BUF (32 * SBH)
#define STAGES 3
#define GEMM_SMEM ((STAGES * (A_BUF + B_BUF)) * 2)   // 87552 bytes

__device__ __forceinline__ void ldm_x4(uint32_t* r, uint32_t addr) {
    asm volatile("ldmatrix.sync.aligned.m8n8.x4.shared.b16 {%0,%1,%2,%3}, [%4];"
                 : "=r"(r[0]), "=r"(r[1]), "=r"(r[2]), "=r"(r[3]) : "r"(addr));
}
__device__ __forceinline__ void ldm_x4_t(uint32_t* r, uint32_t addr) {
    asm volatile("ldmatrix.sync.aligned.m8n8.x4.trans.shared.b16 {%0,%1,%2,%3}, [%4];"
                 : "=r"(r[0]), "=r"(r[1]), "=r"(r[2]), "=r"(r[3]) : "r"(addr));
}
__device__ __forceinline__ void mma_f16(float* c, uint32_t a0, uint32_t a1,
                                        uint32_t a2, uint32_t a3,
                                        uint32_t b0, uint32_t b1) {
    asm volatile(
        "mma.sync.aligned.m16n8k16.row.col.f32.f16.f16.f32 "
        "{%0,%1,%2,%3},{%4,%5,%6,%7},{%8,%9},{%0,%1,%2,%3};\n"
        : "+f"(c[0]), "+f"(c[1]), "+f"(c[2]), "+f"(c[3])
        : "r"(a0), "r"(a1), "r"(a2), "r"(a3), "r"(b0), "r"(b1));
}
__device__ __forceinline__ void cp16(uint32_t dst, const void* src, bool ok) {
    int sz = ok ? 16 : 0;
    asm volatile("cp.async.ca.shared.global [%0], [%1], 16, %2;"
                 :: "r"(dst), "l"(src), "r"(sz));
}

template <int HPB, bool HALFOUT>
__global__ __launch_bounds__(256) void gemm_f16_kernel(
    int M, int N, int K,
    const __half* __restrict__ A, const __half* __restrict__ B,
    float* __restrict__ Cf, __half* __restrict__ Chalf,
    int ldc, int ncols, const float* __restrict__ bias,
    const float* __restrict__ avs, const float* __restrict__ avd,
    float* __restrict__ o_src, float* __restrict__ o_dst)
{
    extern __shared__ __half smem[];
    uint32_t smem_u32 = (uint32_t)__cvta_generic_to_shared(smem);

    int tid  = threadIdx.x;
    int row0 = blockIdx.y * 256;
    int col0 = blockIdx.x * 128;
    int warp = tid >> 5, lane = tid & 31;
    int wm = warp >> 1, wn = warp & 1;       // 4x2 warps -> warp tile 64x64
    int tg = lane >> 2, tig = lane & 3;

    bool aok = (row0 + tid) < M;

    auto issue = [&](int kt, int buf) {
        const __half* asrc = A + (size_t)(row0 + tid) * K + kt * 32;
        uint32_t adst = smem_u32 + (uint32_t)((buf * A_BUF + tid * SAH) * 2);
        #pragma unroll
        for (int i = 0; i < 4; i++)
            cp16(adst + i * 16, asrc + i * 8, aok);
        int brow = tid >> 3, bch = (tid & 7) * 2;
        const __half* bsrc = B + (size_t)(kt * 32 + brow) * N + col0 + bch * 8;
        uint32_t bdst = smem_u32 +
            (uint32_t)((STAGES * A_BUF + buf * B_BUF + brow * SBH + bch * 8) * 2);
        cp16(bdst,      bsrc,     true);
        cp16(bdst + 16, bsrc + 8, true);
        asm volatile("cp.async.commit_group;");
    };

    float c[4][8][4];
    #pragma unroll
    for (int mi = 0; mi < 4; mi++)
        #pragma unroll
        for (int ni = 0; ni < 8; ni++)
            #pragma unroll
            for (int j = 0; j < 4; j++) c[mi][ni][j] = 0.0f;

    int la = lane & 15, lh = lane >> 4;
    uint32_t a_lane = (uint32_t)((la * SAH + lh * 8) * 2);
    uint32_t b_lane = (uint32_t)((la * SBH + lh * 8) * 2);

    auto compute = [&](int buf) {
        uint32_t sa = smem_u32 + (uint32_t)(buf * A_BUF * 2) + a_lane
                    + (uint32_t)(wm * 64 * SAH * 2);
        uint32_t sb = smem_u32 + (uint32_t)((STAGES * A_BUF + buf * B_BUF) * 2) + b_lane
                    + (uint32_t)(wn * 64 * 2);
        #pragma unroll
        for (int ks = 0; ks < 2; ks++) {
            int kk = ks * 16;
            uint32_t af[4][4], bf[4][4];
            #pragma unroll
            for (int mi = 0; mi < 4; mi++)
                ldm_x4(af[mi], sa + (uint32_t)((mi * 16 * SAH + kk) * 2));
            #pragma unroll
            for (int np = 0; np < 4; np++)
                ldm_x4_t(bf[np], sb + (uint32_t)((kk * SBH + np * 16) * 2));
            #pragma unroll
            for (int mi = 0; mi < 4; mi++)
                #pragma unroll
                for (int np = 0; np < 4; np++) {
                    mma_f16(c[mi][np * 2],     af[mi][0], af[mi][1], af[mi][2], af[mi][3],
                            bf[np][0], bf[np][1]);
                    mma_f16(c[mi][np * 2 + 1], af[mi][0], af[mi][1], af[mi][2], af[mi][3],
                            bf[np][2], bf[np][3]);
                }
        }
    };

    int KT = K / 32;
    issue(0, 0);
    issue(1, 1);
    asm volatile("cp.async.wait_group 1;");
    __syncthreads();

    int cbuf = 0, wbuf = 2;
    for (int kt = 0; kt < KT; kt++) {
        compute(cbuf);
        if (kt + 2 < KT) {
            issue(kt + 2, wbuf);
            asm volatile("cp.async.wait_group 1;");
        } else {
            asm volatile("cp.async.wait_group 0;");
        }
        __syncthreads();
        cbuf = (cbuf == 2) ? 0 : cbuf + 1;
        wbuf = (wbuf == 2) ? 0 : wbuf + 1;
    }

    // ---- fused attention-coefficient epilogue (overlay dead smem) ----
    if (HPB > 0) {
        float* sm_src = (float*)smem;          // [2][256]
        float* sm_dst = sm_src + 512;          // [2][256]
        float sa_[4][2], da_[4][2];
        #pragma unroll
        for (int mi = 0; mi < 4; mi++) {
            sa_[mi][0] = sa_[mi][1] = 0.f;
            da_[mi][0] = da_[mi][1] = 0.f;
        }
        #pragma unroll
        for (int ni = 0; ni < 8; ni++) {
            int cl = wn * 64 + ni * 8 + tig * 2;
            float ws0 = avs[col0 + cl], ws1 = avs[col0 + cl + 1];
            float wd0 = avd[col0 + cl], wd1 = avd[col0 + cl + 1];
            #pragma unroll
            for (int mi = 0; mi < 4; mi++) {
                sa_[mi][0] += c[mi][ni][0] * ws0 + c[mi][ni][1] * ws1;
                da_[mi][0] += c[mi][ni][0] * wd0 + c[mi][ni][1] * wd1;
                sa_[mi][1] += c[mi][ni][2] * ws0 + c[mi][ni][3] * ws1;
                da_[mi][1] += c[mi][ni][2] * wd0 + c[mi][ni][3] * wd1;
            }
        }
        #pragma unroll
        for (int mi = 0; mi < 4; mi++)
            #pragma unroll
            for (int p = 0; p < 2; p++) {
                sa_[mi][p] += __shfl_xor_sync(0xffffffffu, sa_[mi][p], 1);
                sa_[mi][p] += __shfl_xor_sync(0xffffffffu, sa_[mi][p], 2);
                da_[mi][p] += __shfl_xor_sync(0xffffffffu, da_[mi][p], 1);
                da_[mi][p] += __shfl_xor_sync(0xffffffffu, da_[mi][p], 2);
            }
        if (tig == 0) {
            #pragma unroll
            for (int mi = 0; mi < 4; mi++) {
                int rl = wm * 64 + mi * 16 + tg;
                sm_src[wn * 256 + rl]     = sa_[mi][0];
                sm_src[wn * 256 + rl + 8] = sa_[mi][1];
                sm_dst[wn * 256 + rl]     = da_[mi][0];
                sm_dst[wn * 256 + rl + 8] = da_[mi][1];
            }
        }
        __syncthreads();
        {
            int r = row0 + tid;
            if (r < M) {
                if (HPB == 1) {
                    o_src[r * HH + blockIdx.x] = sm_src[tid] + sm_src[256 + tid];
                    o_dst[r * HH + blockIdx.x] = sm_dst[tid] + sm_dst[256 + tid];
                } else {
                    int hb = blockIdx.x * 2;
                    o_src[r * HH + hb]     = sm_src[tid];
                    o_src[r * HH + hb + 1] = sm_src[256 + tid];
                    o_dst[r * HH + hb]     = sm_dst[tid];
                    o_dst[r * HH + hb + 1] = sm_dst[256 + tid];
                }
            }
        }
    }

    // ---- C write ----
    #pragma unroll
    for (int mi = 0; mi < 4; mi++) {
        int r = row0 + wm * 64 + mi * 16 + tg;
        #pragma unroll
        for (int ni = 0; ni < 8; ni++) {
            int cc = col0 + wn * 64 + ni * 8 + tig * 2;
            if (cc >= ncols) continue;
            if (HALFOUT) {
                if (r < M)
                    *(__half2*)(Chalf + (size_t)r * ldc + cc) =
                        __floats2half2_rn(c[mi][ni][0], c[mi][ni][1]);
                if (r + 8 < M)
                    *(__half2*)(Chalf + (size_t)(r + 8) * ldc + cc) =
                        __floats2half2_rn(c[mi][ni][2], c[mi][ni][3]);
            } else {
                float b0 = bias ? bias[cc]     : 0.f;
                float b1 = bias ? bias[cc + 1] : 0.f;
                if (r < M) {
                    Cf[(size_t)r * ldc + cc]     = c[mi][ni][0] + b0;
                    Cf[(size_t)r * ldc + cc + 1] = c[mi][ni][1] + b1;
                }
                if (r + 8 < M) {
                    Cf[(size_t)(r + 8) * ldc + cc]     = c[mi][ni][2] + b0;
                    Cf[(size_t)(r + 8) * ldc + cc + 1] = c[mi][ni][3] + b1;
                }
            }
        }
    }
}

// ---------------- GAT softmax + aggregation (one block per dst node) --------
#define DCAP 512
template <int CH>
__global__ __launch_bounds__(128) void gat_agg_kernel(
    const __half* __restrict__ h,
    const float* __restrict__ asrc, const float* __restrict__ adst,
    const float* __restrict__ bias, __half* __restrict__ out)
{
    constexpr int VEC = CH / 128;             // 4 (layer1) or 2 (layer2)
    __shared__ int   ssrc[DCAP];
    __shared__ float sexp[DCAP * HH];
    __shared__ float red[4][HH];

    int d    = blockIdx.x;
    int tid  = threadIdx.x;
    int lane = tid & 31, warp = tid >> 5;
    int s0   = g_rowptr[d];
    int deg  = g_rowptr[d + 1] - s0;

    float4 ad4 = *(const float4*)&adst[d * HH];

    float sm[HH] = {0.f, 0.f, 0.f, 0.f};
    if (deg <= DCAP) {
        for (int j = tid; j < deg; j += 128) {
            int s = g_csr[s0 + j];
            ssrc[j] = s;
            float4 a = *(const float4*)&asrc[s * HH];
            float e0 = a.x + ad4.x; e0 = (e0 > 0.f) ? e0 : SLOPE * e0; e0 = __expf(e0);
            float e1 = a.y + ad4.y; e1 = (e1 > 0.f) ? e1 : SLOPE * e1; e1 = __expf(e1);
            float e2 = a.z + ad4.z; e2 = (e2 > 0.f) ? e2 : SLOPE * e2; e2 = __expf(e2);
            float e3 = a.w + ad4.w; e3 = (e3 > 0.f) ? e3 : SLOPE * e3; e3 = __expf(e3);
            sexp[j * HH + 0] = e0; sexp[j * HH + 1] = e1;
            sexp[j * HH + 2] = e2; sexp[j * HH + 3] = e3;
            sm[0] += e0; sm[1] += e1; sm[2] += e2; sm[3] += e3;
        }
    } else {
        for (int j = tid; j < deg; j += 128) {
            int s = g_csr[s0 + j];
            float4 a = *(const float4*)&asrc[s * HH];
            float e0 = a.x + ad4.x; e0 = (e0 > 0.f) ? e0 : SLOPE * e0;
            float e1 = a.y + ad4.y; e1 = (e1 > 0.f) ? e1 : SLOPE * e1;
            float e2 = a.z + ad4.z; e2 = (e2 > 0.f) ? e2 : SLOPE * e2;
            float e3 = a.w + ad4.w; e3 = (e3 > 0.f) ? e3 : SLOPE * e3;
            sm[0] += __expf(e0); sm[1] += __expf(e1);
            sm[2] += __expf(e2); sm[3] += __expf(e3);
        }
    }
    #pragma unroll
    for (int hh = 0; hh < HH; hh++)
        #pragma unroll
        for (int off = 16; off > 0; off >>= 1)
            sm[hh] += __shfl_xor_sync(0xffffffffu, sm[hh], off);
    if (lane == 0)
        #pragma unroll
        for (int hh = 0; hh < HH; hh++) red[warp][hh] = sm[hh];
    __syncthreads();   // also publishes ssrc/sexp

    int head = tid >> 5;
    float ih = 1.0f / (red[0][head] + red[1][head] + red[2][head] + red[3][head] + 1e-16f);

    float acc[VEC];
    #pragma unroll
    for (int j = 0; j < VEC; j++) acc[j] = 0.f;

    const int hoff = tid * (VEC / 2);   // __half2 offset within row

    if (deg <= DCAP) {
        int j = 0;
        for (; j + 4 <= deg; j += 4) {
            int sA = ssrc[j], sB = ssrc[j + 1], sC = ssrc[j + 2], sD = ssrc[j + 3];
            float eA = sexp[(j    ) * HH + head];
            float eB = sexp[(j + 1) * HH + head];
            float eC = sexp[(j + 2) * HH + head];
            float eD = sexp[(j + 3) * HH + head];
            const __half2* pA = (const __half2*)(h + (size_t)sA * CH) + hoff;
            const __half2* pB = (const __half2*)(h + (size_t)sB * CH) + hoff;
            const __half2* pC = (const __half2*)(h + (size_t)sC * CH) + hoff;
            const __half2* pD = (const __half2*)(h + (size_t)sD * CH) + hoff;
            if (VEC == 4) {
                __half2 a0 = pA[0], a1 = pA[1];
                __half2 b0 = pB[0], b1 = pB[1];
                __half2 c0 = pC[0], c1 = pC[1];
                __half2 d0 = pD[0], d1 = pD[1];
                float2 f;
                f = __half22float2(a0); acc[0] += eA * f.x; acc[1] += eA * f.y;
                f = __half22float2(a1); acc[2] += eA * f.x; acc[3] += eA * f.y;
                f = __half22float2(b0); acc[0] += eB * f.x; acc[1] += eB * f.y;
                f = __half22float2(b1); acc[2] += eB * f.x; acc[3] += eB * f.y;
                f = __half22float2(c0); acc[0] += eC * f.x; acc[1] += eC * f.y;
                f = __half22float2(c1); acc[2] += eC * f.x; acc[3] += eC * f.y;
                f = __half22float2(d0); acc[0] += eD * f.x; acc[1] += eD * f.y;
                f = __half22float2(d1); acc[2] += eD * f.x; acc[3] += eD * f.y;
            } else {
                __half2 a0 = pA[0], b0 = pB[0], c0 = pC[0], d0 = pD[0];
                float2 f;
                f = __half22float2(a0); acc[0] += eA * f.x; acc[1] += eA * f.y;
                f = __half22float2(b0); acc[0] += eB * f.x; acc[1] += eB * f.y;
                f = __half22float2(c0); acc[0] += eC * f.x; acc[1] += eC * f.y;
                f = __half22float2(d0); acc[0] += eD * f.x; acc[1] += eD * f.y;
            }
        }
        for (; j < deg; j++) {
            int s = ssrc[j];
            float e = sexp[j * HH + head];
            const __half2* p = (const __half2*)(h + (size_t)s * CH) + hoff;
            #pragma unroll
            for (int q = 0; q < VEC / 2; q++) {
                float2 f = __half22float2(p[q]);
                acc[q * 2]     += e * f.x;
                acc[q * 2 + 1] += e * f.y;
            }
        }
    } else {
        for (int c0 = 0; c0 < deg; c0 += DCAP) {
            int cn = min(DCAP, deg - c0);
            __syncthreads();
            for (int j = tid; j < cn; j += 128) {
                int s = g_csr[s0 + c0 + j];
                ssrc[j] = s;
                float4 a = *(const float4*)&asrc[s * HH];
                float e0 = a.x + ad4.x; e0 = (e0 > 0.f) ? e0 : SLOPE * e0;
                float e1 = a.y + ad4.y; e1 = (e1 > 0.f) ? e1 : SLOPE * e1;
                float e2 = a.z + ad4.z; e2 = (e2 > 0.f) ? e2 : SLOPE * e2;
                float e3 = a.w + ad4.w; e3 = (e3 > 0.f) ? e3 : SLOPE * e3;
                sexp[j * HH + 0] = __expf(e0); sexp[j * HH + 1] = __expf(e1);
                sexp[j * HH + 2] = __expf(e2); sexp[j * HH + 3] = __expf(e3);
            }
            __syncthreads();
            for (int j = 0; j < cn; j++) {
                int s = ssrc[j];
                float e = sexp[j * HH + head];
                const __half2* p = (const __half2*)(h + (size_t)s * CH) + hoff;
                #pragma unroll
                for (int q = 0; q < VEC / 2; q++) {
                    float2 f = __half22float2(p[q]);
                    acc[q * 2]     += e * f.x;
                    acc[q * 2 + 1] += e * f.y;
                }
            }
        }
    }

    // elu + bias, write fp16
    float v0 = acc[0] * ih + bias[tid * VEC + 0];
    float v1 = acc[1] * ih + bias[tid * VEC + 1];
    v0 = (v0 > 0.f) ? v0 : expm1f(v0);
    v1 = (v1 > 0.f) ? v1 : expm1f(v1);
    __half2* op = (__half2*)(out + (size_t)d * CH + tid * VEC);
    op[0] = __floats2half2_rn(v0, v1);
    if (VEC == 4) {
        float v2 = acc[2] * ih + bias[tid * VEC + 2];
        float v3 = acc[3] * ih + bias[tid * VEC + 3];
        v2 = (v2 > 0.f) ? v2 : expm1f(v2);
        v3 = (v3 > 0.f) ? v3 : expm1f(v3);
        op[1] = __floats2half2_rn(v2, v3);
    }
}

// ---------------- launch ----------------------------------------------------
extern "C" void kernel_launch(void* const* d_in, const int* in_sizes, int n_in,
                              void* d_out, int out_size)
{
    const float* x   = (const float*)d_in[0];
    const int*   ei  = (const int*)  d_in[1];
    const float* W1  = (const float*)d_in[2];
    const float* as1 = (const float*)d_in[3];
    const float* ad1 = (const float*)d_in[4];
    const float* b1  = (const float*)d_in[5];
    const float* W2  = (const float*)d_in[6];
    const float* as2 = (const float*)d_in[7];
    const float* ad2 = (const float*)d_in[8];
    const float* b2  = (const float*)d_in[9];
    const float* Wf  = (const float*)d_in[10];
    const float* bf  = (const float*)d_in[11];
    float* out = (float*)d_out;

    __half *xh, *W1h, *W2h, *Wfh, *h1h, *h2h, *g1h, *g2h;
    float *pas, *pad;
    cudaGetSymbolAddress((void**)&xh,  g_xh);
    cudaGetSymbolAddress((void**)&W1h, g_W1h);
    cudaGetSymbolAddress((void**)&W2h, g_W2h);
    cudaGetSymbolAddress((void**)&Wfh, g_Wfh);
    cudaGetSymbolAddress((void**)&h1h, g_h1h);
    cudaGetSymbolAddress((void**)&h2h, g_h2h);
    cudaGetSymbolAddress((void**)&g1h, g_g1h);
    cudaGetSymbolAddress((void**)&g2h, g_g2h);
    cudaGetSymbolAddress((void**)&pas, g_asrc);
    cudaGetSymbolAddress((void**)&pad, g_adst);

    cudaFuncSetAttribute(gemm_f16_kernel<1, true>,
                         cudaFuncAttributeMaxDynamicSharedMemorySize, GEMM_SMEM);
    cudaFuncSetAttribute(gemm_f16_kernel<2, true>,
                         cudaFuncAttributeMaxDynamicSharedMemorySize, GEMM_SMEM);
    cudaFuncSetAttribute(gemm_f16_kernel<0, false>,
                         cudaFuncAttributeMaxDynamicSharedMemorySize, GEMM_SMEM);

    // Side stream + events for CSR/GEMM overlap. Created once on the first
    // call (the correctness run, outside graph capture); the captured work
    // is identical on every call.
    static cudaStream_t s2 = nullptr;
    static cudaEvent_t ev_fork = nullptr, ev_join = nullptr;
    if (s2 == nullptr) {
        cudaStreamCreateWithFlags(&s2, cudaStreamNonBlocking);
        cudaEventCreateWithFlags(&ev_fork, cudaEventDisableTiming);
        cudaEventCreateWithFlags(&ev_join, cudaEventDisableTiming);
    }

    int grid_y = (NN + 255) / 256;   // 196
    cudaStream_t s0 = (cudaStream_t)0;   // legacy default stream (captured)

    // ---- fork: CSR build on s2, convert+GEMM1 on main stream ----
    cudaEventRecord(ev_fork, s0);
    cudaStreamWaitEvent(s2, ev_fork, 0);

    // main: convert (launch #1)
    convert_inputs_kernel<<<(NN * FIN / 4 + 255) / 256, 256, 0, s0>>>(x, W1, W2, Wf);
    // s2: CSR chain start (launches #2, #3)
    zero_deg_kernel<<<(NN + 255) / 256, 256, 0, s2>>>();
    count_deg_kernel<<<(ETOT + 255) / 256, 256, 0, s2>>>(ei);
    // main: GEMM1 (launch #4 — keeps ncu fixed-skip capture on GEMM1)
    gemm_f16_kernel<1, true><<<dim3(CH1 / 128, grid_y), 256, GEMM_SMEM, s0>>>(
        NN, CH1, FIN, xh, W1h, (float*)nullptr, h1h, CH1, CH1, (const float*)nullptr,
        as1, ad1, pas, pad);
    // s2: rest of CSR chain
    scan1_kernel<<<NBLK, 256, 0, s2>>>();
    scan2_kernel<<<1, 256, 0, s2>>>();
    scan3_kernel<<<NBLK, 256, 0, s2>>>();
    scatter_edges_kernel<<<(ETOT + 255) / 256, 256, 0, s2>>>(ei);
    cudaEventRecord(ev_join, s2);

    // ---- join: agg1 needs both GEMM1 (main) and CSR (s2) ----
    cudaStreamWaitEvent(s0, ev_join, 0);

    gat_agg_kernel<CH1><<<NN, 128, 0, s0>>>(h1h, pas, pad, b1, g1h);

    // Layer 2
    gemm_f16_kernel<2, true><<<dim3(CH2 / 128, grid_y), 256, GEMM_SMEM, s0>>>(
        NN, CH2, CH1, g1h, W2h, (float*)nullptr, h2h, CH2, CH2, (const float*)nullptr,
        as2, ad2, pas, pad);
    gat_agg_kernel<CH2><<<NN, 128, 0, s0>>>(h2h, pas, pad, b2, g2h);

    // Final classifier: out[N,50] = g2 @ Wfpad + bf
    gemm_f16_kernel<0, false><<<dim3(1, grid_y), 256, GEMM_SMEM, s0>>>(
        NN, 128, CH2, g2h, Wfh, out, (__half*)nullptr, NCLS, NCLS, bf,
        (const float*)nullptr, (const float*)nullptr,
        (float*)nullptr, (float*)nullptr);
}